// round 3
// baseline (speedup 1.0000x reference)
#include <cuda_runtime.h>

#define NN 50000
#define NE 800000
#define NG 512

// ---------------- scratch (static device globals; float4 => 16B aligned) ----------------
__device__ float  g_deg[NN];
__device__ float  g_dinv[NN];
__device__ int    g_src[NE];
__device__ int    g_dst[NE];
__device__ float  g_coef[NE];
__device__ float4 g_agg [(size_t)NN * 256 / 4];   // aggregation buffer (max F_in = 256)
__device__ float4 g_h1  [(size_t)NN * 128 / 4];
__device__ float4 g_h2  [(size_t)NN * 256 / 4];
__device__ float4 g_h3  [(size_t)NN * 512 / 4];
__device__ float4 g_pool[NG * 512 / 4];
__device__ float4 g_fc1 [NG * 1024 / 4];
__device__ int    g_gstart[NG + 1];

// ---------------- degree / normalization prep ----------------
__global__ void k_deg_init(float* deg) {
    int i = blockIdx.x * blockDim.x + threadIdx.x;
    if (i < NN) deg[i] = 1.0f;  // self-loop weight
}

__global__ void k_deg_edges(const int* __restrict__ ei,
                            const float* __restrict__ ew, float* deg) {
    int e = blockIdx.x * blockDim.x + threadIdx.x;
    if (e < NE) atomicAdd(&deg[ei[NE + e]], ew[e]);
}

__global__ void k_dinv(const float* __restrict__ deg, float* dinv) {
    int i = blockIdx.x * blockDim.x + threadIdx.x;
    if (i < NN) {
        float d = deg[i];
        dinv[i] = (d > 0.f) ? rsqrtf(d) : 0.f;
    }
}

__global__ void k_edge_prep(const int* __restrict__ ei,
                            const float* __restrict__ ew,
                            const float* __restrict__ dinv,
                            int* __restrict__ src, int* __restrict__ dst,
                            float* __restrict__ coef) {
    int e = blockIdx.x * blockDim.x + threadIdx.x;
    if (e >= NE) return;
    int s = ei[e];
    int d = ei[NE + e];
    src[e] = s;
    dst[e] = d;
    coef[e] = dinv[s] * ew[e] * dinv[d];
}

// ---------------- aggregation:  agg = D^-1/2 (A + I) D^-1/2 * h ----------------
// init: self-loop term (non-atomic)
template <int F>
__global__ void k_agg_init(const float* __restrict__ h,
                           const float* __restrict__ dinv,
                           float* __restrict__ out) {
    int idx = blockIdx.x * blockDim.x + threadIdx.x;  // over NN * F/4
    if (idx >= NN * (F / 4)) return;
    int v = idx / (F / 4);
    float s = dinv[v];
    s *= s;
    float4 hv = ((const float4*)h)[idx];
    ((float4*)out)[idx] = make_float4(hv.x * s, hv.y * s, hv.z * s, hv.w * s);
}

// edges: one warp per edge, vectorized global reductions
template <int F>
__global__ void k_agg_edges(const int* __restrict__ src, const int* __restrict__ dst,
                            const float* __restrict__ coef,
                            const float* __restrict__ h, float* __restrict__ out) {
    int g = blockIdx.x * blockDim.x + threadIdx.x;
    int e = g >> 5;
    int lane = g & 31;
    if (e >= NE) return;
    int s = src[e];
    int d = dst[e];
    float c = coef[e];
    const float4* hs = (const float4*)(h + (size_t)s * F);
    float4* od = (float4*)(out + (size_t)d * F);
#pragma unroll
    for (int i = lane; i < F / 4; i += 32) {
        float4 v = hs[i];
        asm volatile("red.global.add.v4.f32 [%0], {%1,%2,%3,%4};" ::"l"(od + i),
                     "f"(v.x * c), "f"(v.y * c), "f"(v.z * c), "f"(v.w * c)
                     : "memory");
    }
}

// ---------------- tiled SGEMM + bias + optional relu ----------------
// C[M,N] = A[M,K] @ B[K,N] + bias ; row-major everything. N,K multiples of BN,BK.
template <int BM, int BN, int BK, int TM, int TN>
__global__ void __launch_bounds__((BM / TM) * (BN / TN))
k_gemm_bias_act(const float* __restrict__ A, const float* __restrict__ B,
                const float* __restrict__ bias, float* __restrict__ C,
                int M, int N, int K, int relu) {
    constexpr int THREADS = (BM / TM) * (BN / TN);
    __shared__ float As[BK][BM];
    __shared__ float Bs[BK][BN];
    const int tid = threadIdx.x;
    const int rowBase = blockIdx.y * BM;
    const int colBase = blockIdx.x * BN;
    const int tRow = (tid / (BN / TN)) * TM;
    const int tCol = (tid % (BN / TN)) * TN;
    float acc[TM][TN] = {};

    for (int k0 = 0; k0 < K; k0 += BK) {
#pragma unroll
        for (int i = tid; i < BM * BK / 4; i += THREADS) {
            int r = i / (BK / 4);
            int c4 = (i % (BK / 4)) * 4;
            int gr = rowBase + r;
            float4 v = (gr < M) ? *(const float4*)(A + (size_t)gr * K + k0 + c4)
                                : make_float4(0.f, 0.f, 0.f, 0.f);
            As[c4 + 0][r] = v.x;
            As[c4 + 1][r] = v.y;
            As[c4 + 2][r] = v.z;
            As[c4 + 3][r] = v.w;
        }
#pragma unroll
        for (int i = tid; i < BK * BN / 4; i += THREADS) {
            int r = i / (BN / 4);
            int c4 = (i % (BN / 4)) * 4;
            *(float4*)&Bs[r][c4] = *(const float4*)(B + (size_t)(k0 + r) * N + colBase + c4);
        }
        __syncthreads();
#pragma unroll
        for (int k = 0; k < BK; k++) {
            float ra[TM], rb[TN];
#pragma unroll
            for (int i = 0; i < TM; i += 4) {
                float4 t = *(const float4*)&As[k][tRow + i];
                ra[i] = t.x; ra[i + 1] = t.y; ra[i + 2] = t.z; ra[i + 3] = t.w;
            }
#pragma unroll
            for (int j = 0; j < TN; j += 4) {
                float4 t = *(const float4*)&Bs[k][tCol + j];
                rb[j] = t.x; rb[j + 1] = t.y; rb[j + 2] = t.z; rb[j + 3] = t.w;
            }
#pragma unroll
            for (int i = 0; i < TM; i++)
#pragma unroll
                for (int j = 0; j < TN; j++) acc[i][j] += ra[i] * rb[j];
        }
        __syncthreads();
    }

#pragma unroll
    for (int i = 0; i < TM; i++) {
        int gr = rowBase + tRow + i;
        if (gr >= M) break;
#pragma unroll
        for (int j = 0; j < TN; j += 4) {
            int gc = colBase + tCol + j;
            float4 v;
            v.x = acc[i][j + 0] + bias[gc + 0];
            v.y = acc[i][j + 1] + bias[gc + 1];
            v.z = acc[i][j + 2] + bias[gc + 2];
            v.w = acc[i][j + 3] + bias[gc + 3];
            if (relu) {
                v.x = fmaxf(v.x, 0.f); v.y = fmaxf(v.y, 0.f);
                v.z = fmaxf(v.z, 0.f); v.w = fmaxf(v.w, 0.f);
            }
            *(float4*)(C + (size_t)gr * N + gc) = v;
        }
    }
}

// ---------------- global max pool (batch is sorted) ----------------
__global__ void k_gstart(const int* __restrict__ batch, int* __restrict__ gstart) {
    int i = blockIdx.x * blockDim.x + threadIdx.x;
    if (i >= NN) return;
    if (i == 0) {
        gstart[0] = 0;
        gstart[NG] = NN;
    } else if (batch[i] != batch[i - 1]) {
        gstart[batch[i]] = i;
    }
}

__global__ void k_pool_max(const float* __restrict__ h, const int* __restrict__ gstart,
                           float* __restrict__ g) {
    int gr = blockIdx.x;   // graph
    int f = threadIdx.x;   // feature (512 threads)
    int s = gstart[gr], e = gstart[gr + 1];
    float m = -3.4e38f;
    for (int i = s; i < e; i++) m = fmaxf(m, h[(size_t)i * 512 + f]);
    g[gr * 512 + f] = m;
}

// ---------------- launch ----------------
extern "C" void kernel_launch(void* const* d_in, const int* in_sizes, int n_in,
                              void* d_out, int out_size) {
    const float* x   = (const float*)d_in[0];
    const float* ew  = (const float*)d_in[1];
    const float* W1  = (const float*)d_in[2];
    const float* b1  = (const float*)d_in[3];
    const float* W2  = (const float*)d_in[4];
    const float* b2  = (const float*)d_in[5];
    const float* W3  = (const float*)d_in[6];
    const float* b3  = (const float*)d_in[7];
    const float* Wf1 = (const float*)d_in[8];
    const float* bf1 = (const float*)d_in[9];
    const float* Wf2 = (const float*)d_in[10];
    const float* bf2 = (const float*)d_in[11];
    const int* ei    = (const int*)d_in[12];    // int32 (JAX x64 disabled)
    const int* batch = (const int*)d_in[13];    // int32
    float* out = (float*)d_out;

    void *p;
    cudaGetSymbolAddress(&p, g_deg);    float* deg  = (float*)p;
    cudaGetSymbolAddress(&p, g_dinv);   float* dinv = (float*)p;
    cudaGetSymbolAddress(&p, g_src);    int*   src  = (int*)p;
    cudaGetSymbolAddress(&p, g_dst);    int*   dst  = (int*)p;
    cudaGetSymbolAddress(&p, g_coef);   float* coef = (float*)p;
    cudaGetSymbolAddress(&p, g_agg);    float* agg  = (float*)p;
    cudaGetSymbolAddress(&p, g_h1);     float* h1   = (float*)p;
    cudaGetSymbolAddress(&p, g_h2);     float* h2   = (float*)p;
    cudaGetSymbolAddress(&p, g_h3);     float* h3   = (float*)p;
    cudaGetSymbolAddress(&p, g_pool);   float* pool = (float*)p;
    cudaGetSymbolAddress(&p, g_fc1);    float* fc1  = (float*)p;
    cudaGetSymbolAddress(&p, g_gstart); int*   gst  = (int*)p;

    const int T = 256;
    // ---- normalization prep (shared by all 3 conv layers) ----
    k_deg_init<<<(NN + T - 1) / T, T>>>(deg);
    k_deg_edges<<<(NE + T - 1) / T, T>>>(ei, ew, deg);
    k_dinv<<<(NN + T - 1) / T, T>>>(deg, dinv);
    k_edge_prep<<<(NE + T - 1) / T, T>>>(ei, ew, dinv, src, dst, coef);

    const int MB = (NN + 127) / 128;  // 391 M-tiles

    // ---- layer 1: agg(x) [F=128] -> @W1[128,128] + b1, relu ----
    k_agg_init<128><<<(NN * 32 + T - 1) / T, T>>>(x, dinv, agg);
    k_agg_edges<128><<<(NE * 32 + T - 1) / T, T>>>(src, dst, coef, x, agg);
    k_gemm_bias_act<128, 128, 16, 8, 8><<<dim3(1, MB), 256>>>(agg, W1, b1, h1, NN, 128, 128, 1);

    // ---- layer 2: agg(h1) [F=128] -> @W2[128,256] + b2, relu ----
    k_agg_init<128><<<(NN * 32 + T - 1) / T, T>>>(h1, dinv, agg);
    k_agg_edges<128><<<(NE * 32 + T - 1) / T, T>>>(src, dst, coef, h1, agg);
    k_gemm_bias_act<128, 128, 16, 8, 8><<<dim3(2, MB), 256>>>(agg, W2, b2, h2, NN, 256, 128, 1);

    // ---- layer 3: agg(h2) [F=256] -> @W3[256,512] + b3, relu ----
    k_agg_init<256><<<(NN * 64 + T - 1) / T, T>>>(h2, dinv, agg);
    k_agg_edges<256><<<(NE * 32 + T - 1) / T, T>>>(src, dst, coef, h2, agg);
    k_gemm_bias_act<128, 128, 16, 8, 8><<<dim3(4, MB), 256>>>(agg, W3, b3, h3, NN, 512, 256, 1);

    // ---- global max pool ----
    k_gstart<<<(NN + T - 1) / T, T>>>(batch, gst);
    k_pool_max<<<NG, 512>>>(h3, gst, pool);

    // ---- FC head ----
    k_gemm_bias_act<64, 64, 16, 4, 4><<<dim3(1024 / 64, NG / 64), 256>>>(pool, Wf1, bf1, fc1, NG, 1024, 512, 1);
    k_gemm_bias_act<64, 64, 16, 4, 4><<<dim3(128 / 64, NG / 64), 256>>>(fc1, Wf2, bf2, out, NG, 128, 1024, 0);
}

// round 5
// speedup vs baseline: 1.5494x; 1.5494x over previous
#include <cuda_runtime.h>
#include <cstdint>

#define NN 50000
#define NE 800000
#define NG 512

// ---------------- scratch (float4 => 16B aligned) ----------------
__device__ float  g_deg[NN];
__device__ float  g_dinv[NN];
__device__ int    g_src[NE];
__device__ int    g_dst[NE];
__device__ float  g_coef[NE];
__device__ float4 g_aggA[(size_t)NN * 128 / 4];   // layer1 input agg (from x)
__device__ float4 g_aggB[(size_t)NN * 128 / 4];   // layer2 input agg (from h1)
__device__ float4 g_aggC[(size_t)NN * 256 / 4];   // layer3 input agg (from h2)
__device__ float4 g_h1  [(size_t)NN * 128 / 4];
__device__ float4 g_h2  [(size_t)NN * 256 / 4];
__device__ float4 g_h3  [(size_t)NN * 512 / 4];
__device__ float4 g_pool[NG * 512 / 4];
__device__ float4 g_fc1 [NG * 1024 / 4];
__device__ int    g_gstart[NG + 1];

// ---------------- degree / normalization prep ----------------
__global__ void k_deg_init(float* deg) {
    int i = blockIdx.x * blockDim.x + threadIdx.x;
    if (i < NN) deg[i] = 1.0f;  // self-loop weight
}

__global__ void k_deg_edges(const int* __restrict__ ei,
                            const float* __restrict__ ew, float* deg) {
    int e = blockIdx.x * blockDim.x + threadIdx.x;
    if (e < NE) atomicAdd(&deg[ei[NE + e]], ew[e]);
}

__global__ void k_dinv(const float* __restrict__ deg, float* dinv) {
    int i = blockIdx.x * blockDim.x + threadIdx.x;
    if (i < NN) {
        float d = deg[i];
        dinv[i] = (d > 0.f) ? rsqrtf(d) : 0.f;
    }
}

__global__ void k_edge_prep(const int* __restrict__ ei,
                            const float* __restrict__ ew,
                            const float* __restrict__ dinv,
                            int* __restrict__ src, int* __restrict__ dst,
                            float* __restrict__ coef) {
    int e = blockIdx.x * blockDim.x + threadIdx.x;
    if (e >= NE) return;
    int s = ei[e];
    int d = ei[NE + e];
    src[e] = s;
    dst[e] = d;
    coef[e] = dinv[s] * ew[e] * dinv[d];
}

// ---------------- aggregation ----------------
// init (only needed for the raw input x): agg = dinv^2 * h
template <int F>
__global__ void k_agg_init(const float* __restrict__ h,
                           const float* __restrict__ dinv,
                           float* __restrict__ out) {
    int idx = blockIdx.x * blockDim.x + threadIdx.x;  // over NN * F/4
    if (idx >= NN * (F / 4)) return;
    int v = idx / (F / 4);
    float s = dinv[v];
    s *= s;
    float4 hv = ((const float4*)h)[idx];
    ((float4*)out)[idx] = make_float4(hv.x * s, hv.y * s, hv.z * s, hv.w * s);
}

// edges: one warp per edge, vectorized global reductions
template <int F>
__global__ void k_agg_edges(const int* __restrict__ src, const int* __restrict__ dst,
                            const float* __restrict__ coef,
                            const float* __restrict__ h, float* __restrict__ out) {
    int g = blockIdx.x * blockDim.x + threadIdx.x;
    int e = g >> 5;
    int lane = g & 31;
    if (e >= NE) return;
    int s = src[e];
    int d = dst[e];
    float c = coef[e];
    const float4* hs = (const float4*)(h + (size_t)s * F);
    float4* od = (float4*)(out + (size_t)d * F);
#pragma unroll
    for (int i = lane; i < F / 4; i += 32) {
        float4 v = hs[i];
        asm volatile("red.global.add.v4.f32 [%0], {%1,%2,%3,%4};" ::"l"(od + i),
                     "f"(v.x * c), "f"(v.y * c), "f"(v.z * c), "f"(v.w * c)
                     : "memory");
    }
}

// ---------------- TF32 tensor-core GEMM + bias + relu (+ fused agg-init) ----------------
// C[M,N] = relu(A[M,K] @ B[K,N] + bias); if aggout: aggout = dinv^2 * C (self-loop init)
// Block tile 128x128, BK=32, 256 threads (8 warps of 64x32). N,K multiples of 128/32.
__device__ __forceinline__ unsigned f2tf(float x) {
    unsigned u;
    asm("cvt.rna.tf32.f32 %0, %1;" : "=r"(u) : "f"(x));
    return u;
}

__global__ void __launch_bounds__(256)
k_gemm_tf32(const float* __restrict__ A, const float* __restrict__ B,
            const float* __restrict__ bias, float* __restrict__ C,
            float* __restrict__ aggout, const float* __restrict__ dinv,
            int M, int N, int K, int relu) {
    __shared__ float As[128][36];    // [m][k], pad 4: frag bank = 4g+t (conflict-free)
    __shared__ float Bs[32][136];    // [k][n], pad 8: frag bank = 8t+g (conflict-free)

    const int tid = threadIdx.x;
    const int wid = tid >> 5, lane = tid & 31;
    const int g = lane >> 2, t = lane & 3;
    const int wr = (wid >> 2) * 64;      // warp row: 0/64
    const int wc = (wid & 3) * 32;       // warp col: 0/32/64/96
    const int rowBase = blockIdx.y * 128;
    const int colBase = blockIdx.x * 128;

    float acc[4][4][4];
#pragma unroll
    for (int i = 0; i < 4; i++)
#pragma unroll
        for (int j = 0; j < 4; j++)
#pragma unroll
            for (int k = 0; k < 4; k++) acc[i][j][k] = 0.f;

    for (int k0 = 0; k0 < K; k0 += 32) {
        // load A tile: thread chunk c -> m = c/8, kc = (c%8)*4
#pragma unroll
        for (int i = 0; i < 4; i++) {
            int c = i * 256 + tid;
            int m = c >> 3, kc = (c & 7) * 4;
            int gr = rowBase + m;
            float4 v = (gr < M) ? *(const float4*)(A + (size_t)gr * K + k0 + kc)
                                : make_float4(0.f, 0.f, 0.f, 0.f);
            As[m][kc + 0] = __uint_as_float(f2tf(v.x));
            As[m][kc + 1] = __uint_as_float(f2tf(v.y));
            As[m][kc + 2] = __uint_as_float(f2tf(v.z));
            As[m][kc + 3] = __uint_as_float(f2tf(v.w));
        }
        // load B tile: thread chunk c -> k = c/32, nc = (c%32)*4
#pragma unroll
        for (int i = 0; i < 4; i++) {
            int c = i * 256 + tid;
            int k = c >> 5, nc = (c & 31) * 4;
            float4 v = *(const float4*)(B + (size_t)(k0 + k) * N + colBase + nc);
            float4 w;
            w.x = __uint_as_float(f2tf(v.x));
            w.y = __uint_as_float(f2tf(v.y));
            w.z = __uint_as_float(f2tf(v.z));
            w.w = __uint_as_float(f2tf(v.w));
            *(float4*)&Bs[k][nc] = w;
        }
        __syncthreads();

#pragma unroll
        for (int kk = 0; kk < 4; kk++) {
            const int kb = kk * 8;
            uint32_t a[4][4], b[4][2];
#pragma unroll
            for (int mi = 0; mi < 4; mi++) {
                int r = wr + mi * 16 + g;
                a[mi][0] = __float_as_uint(As[r][kb + t]);
                a[mi][1] = __float_as_uint(As[r + 8][kb + t]);
                a[mi][2] = __float_as_uint(As[r][kb + t + 4]);
                a[mi][3] = __float_as_uint(As[r + 8][kb + t + 4]);
            }
#pragma unroll
            for (int ni = 0; ni < 4; ni++) {
                int cn = wc + ni * 8 + g;
                b[ni][0] = __float_as_uint(Bs[kb + t][cn]);
                b[ni][1] = __float_as_uint(Bs[kb + t + 4][cn]);
            }
#pragma unroll
            for (int mi = 0; mi < 4; mi++)
#pragma unroll
                for (int ni = 0; ni < 4; ni++) {
                    asm volatile(
                        "mma.sync.aligned.m16n8k8.row.col.f32.tf32.tf32.f32 "
                        "{%0,%1,%2,%3}, {%4,%5,%6,%7}, {%8,%9}, {%0,%1,%2,%3};"
                        : "+f"(acc[mi][ni][0]), "+f"(acc[mi][ni][1]),
                          "+f"(acc[mi][ni][2]), "+f"(acc[mi][ni][3])
                        : "r"(a[mi][0]), "r"(a[mi][1]), "r"(a[mi][2]), "r"(a[mi][3]),
                          "r"(b[ni][0]), "r"(b[ni][1]));
                }
        }
        __syncthreads();
    }

    // epilogue
#pragma unroll
    for (int mi = 0; mi < 4; mi++) {
        int r0 = rowBase + wr + mi * 16 + g;
#pragma unroll
        for (int half = 0; half < 2; half++) {
            int r = r0 + half * 8;
            if (r >= M) continue;
            float s = 0.f;
            if (aggout) {
                s = dinv[r];
                s *= s;
            }
#pragma unroll
            for (int ni = 0; ni < 4; ni++) {
                int col = colBase + wc + ni * 8 + 2 * t;
                float v0 = acc[mi][ni][half * 2 + 0] + bias[col];
                float v1 = acc[mi][ni][half * 2 + 1] + bias[col + 1];
                if (relu) {
                    v0 = fmaxf(v0, 0.f);
                    v1 = fmaxf(v1, 0.f);
                }
                *(float2*)(C + (size_t)r * N + col) = make_float2(v0, v1);
                if (aggout)
                    *(float2*)(aggout + (size_t)r * N + col) = make_float2(s * v0, s * v1);
            }
        }
    }
}

// ---------------- global max pool (batch is sorted) ----------------
__global__ void k_gstart(const int* __restrict__ batch, int* __restrict__ gstart) {
    int i = blockIdx.x * blockDim.x + threadIdx.x;
    if (i >= NN) return;
    if (i == 0) {
        gstart[0] = 0;
        gstart[NG] = NN;
    } else if (batch[i] != batch[i - 1]) {
        gstart[batch[i]] = i;
    }
}

__global__ void k_pool_max(const float* __restrict__ h, const int* __restrict__ gstart,
                           float* __restrict__ g) {
    int gr = blockIdx.x;   // graph
    int f = threadIdx.x;   // feature (512 threads)
    int s = gstart[gr], e = gstart[gr + 1];
    float m = -3.4e38f;
    for (int i = s; i < e; i++) m = fmaxf(m, h[(size_t)i * 512 + f]);
    g[gr * 512 + f] = m;
}

// ---------------- launch ----------------
extern "C" void kernel_launch(void* const* d_in, const int* in_sizes, int n_in,
                              void* d_out, int out_size) {
    const float* x   = (const float*)d_in[0];
    const float* ew  = (const float*)d_in[1];
    const float* W1  = (const float*)d_in[2];
    const float* b1  = (const float*)d_in[3];
    const float* W2  = (const float*)d_in[4];
    const float* b2  = (const float*)d_in[5];
    const float* W3  = (const float*)d_in[6];
    const float* b3  = (const float*)d_in[7];
    const float* Wf1 = (const float*)d_in[8];
    const float* bf1 = (const float*)d_in[9];
    const float* Wf2 = (const float*)d_in[10];
    const float* bf2 = (const float*)d_in[11];
    const int* ei    = (const int*)d_in[12];    // int32 (JAX x64 disabled)
    const int* batch = (const int*)d_in[13];    // int32
    float* out = (float*)d_out;

    void *p;
    cudaGetSymbolAddress(&p, g_deg);    float* deg  = (float*)p;
    cudaGetSymbolAddress(&p, g_dinv);   float* dinv = (float*)p;
    cudaGetSymbolAddress(&p, g_src);    int*   src  = (int*)p;
    cudaGetSymbolAddress(&p, g_dst);    int*   dst  = (int*)p;
    cudaGetSymbolAddress(&p, g_aggA);   float* aggA = (float*)p;
    cudaGetSymbolAddress(&p, g_aggB);   float* aggB = (float*)p;
    cudaGetSymbolAddress(&p, g_aggC);   float* aggC = (float*)p;
    cudaGetSymbolAddress(&p, g_coef);   float* coef = (float*)p;
    cudaGetSymbolAddress(&p, g_h1);     float* h1   = (float*)p;
    cudaGetSymbolAddress(&p, g_h2);     float* h2   = (float*)p;
    cudaGetSymbolAddress(&p, g_h3);     float* h3   = (float*)p;
    cudaGetSymbolAddress(&p, g_pool);   float* pool = (float*)p;
    cudaGetSymbolAddress(&p, g_fc1);    float* fc1  = (float*)p;
    cudaGetSymbolAddress(&p, g_gstart); int*   gst  = (int*)p;

    const int T = 256;
    // ---- normalization prep ----
    k_deg_init<<<(NN + T - 1) / T, T>>>(deg);
    k_deg_edges<<<(NE + T - 1) / T, T>>>(ei, ew, deg);
    k_dinv<<<(NN + T - 1) / T, T>>>(deg, dinv);
    k_edge_prep<<<(NE + T - 1) / T, T>>>(ei, ew, dinv, src, dst, coef);

    const int MB = (NN + 127) / 128;  // 391 row tiles

    // ---- layer 1: agg(x) -> @W1 + b1, relu; epilogue pre-inits aggB ----
    k_agg_init<128><<<(NN * 32 + T - 1) / T, T>>>(x, dinv, aggA);
    k_agg_edges<128><<<(NE * 32 + T - 1) / T, T>>>(src, dst, coef, x, aggA);
    k_gemm_tf32<<<dim3(1, MB), 256>>>(aggA, W1, b1, h1, aggB, dinv, NN, 128, 128, 1);

    // ---- layer 2 ----
    k_agg_edges<128><<<(NE * 32 + T - 1) / T, T>>>(src, dst, coef, h1, aggB);
    k_gemm_tf32<<<dim3(2, MB), 256>>>(aggB, W2, b2, h2, aggC, dinv, NN, 256, 128, 1);

    // ---- layer 3 ----
    k_agg_edges<256><<<(NE * 32 + T - 1) / T, T>>>(src, dst, coef, h2, aggC);
    k_gemm_tf32<<<dim3(4, MB), 256>>>(aggC, W3, b3, h3, nullptr, dinv, NN, 512, 256, 1);

    // ---- global max pool ----
    k_gstart<<<(NN + T - 1) / T, T>>>(batch, gst);
    k_pool_max<<<NG, 512>>>(h3, gst, pool);

    // ---- FC head ----
    k_gemm_tf32<<<dim3(8, 4), 256>>>(pool, Wf1, bf1, fc1, nullptr, dinv, NG, 1024, 512, 1);
    k_gemm_tf32<<<dim3(1, 4), 256>>>(fc1, Wf2, bf2, out, nullptr, dinv, NG, 128, 1024, 0);
}

// round 6
// speedup vs baseline: 1.8387x; 1.1867x over previous
#include <cuda_runtime.h>
#include <cstdint>

#define NN 50000
#define NE 800000
#define NG 512

// ---------------- scratch (float4 => 16B aligned) ----------------
__device__ float  g_deg[NN];
__device__ float  g_dinv[NN];
__device__ int    g_cnt[NN];          // edge counts, reused as scatter cursor
__device__ int    g_rowptr[NN + 1];
__device__ int    g_dst[NE];
__device__ int    g_esrc[NE];         // CSR-sorted src
__device__ float  g_ecoef[NE];        // CSR-sorted coef
__device__ int    g_tsrc[NE];         // unsorted temporaries
__device__ float  g_tcoef[NE];
__device__ float4 g_agg [(size_t)NN * 256 / 4];   // aggregation buffer (max F_in = 256)
__device__ float4 g_h1  [(size_t)NN * 128 / 4];
__device__ float4 g_h2  [(size_t)NN * 256 / 4];
__device__ float4 g_h3  [(size_t)NN * 512 / 4];
__device__ float4 g_pool[NG * 512 / 4];
__device__ float4 g_fc1 [NG * 1024 / 4];
__device__ int    g_gstart[NG + 1];

// ---------------- degree / normalization prep ----------------
__global__ void k_deg_init(float* deg, int* cnt) {
    int i = blockIdx.x * blockDim.x + threadIdx.x;
    if (i < NN) {
        deg[i] = 1.0f;  // self-loop weight
        cnt[i] = 0;
    }
}

__global__ void k_deg_edges(const int* __restrict__ ei,
                            const float* __restrict__ ew, float* deg) {
    int e = blockIdx.x * blockDim.x + threadIdx.x;
    if (e < NE) atomicAdd(&deg[ei[NE + e]], ew[e]);
}

__global__ void k_dinv(const float* __restrict__ deg, float* dinv) {
    int i = blockIdx.x * blockDim.x + threadIdx.x;
    if (i < NN) {
        float d = deg[i];
        dinv[i] = (d > 0.f) ? rsqrtf(d) : 0.f;
    }
}

// coef per edge + per-dst edge count (for CSR)
__global__ void k_edge_prep(const int* __restrict__ ei,
                            const float* __restrict__ ew,
                            const float* __restrict__ dinv,
                            int* __restrict__ dst, int* __restrict__ tsrc,
                            float* __restrict__ tcoef, int* __restrict__ cnt) {
    int e = blockIdx.x * blockDim.x + threadIdx.x;
    if (e >= NE) return;
    int s = ei[e];
    int d = ei[NE + e];
    dst[e] = d;
    tsrc[e] = s;
    tcoef[e] = dinv[s] * ew[e] * dinv[d];
    atomicAdd(&cnt[d], 1);
}

// single-block exclusive scan over cnt[NN] -> rowptr; zeroes cnt for cursor reuse
__global__ void k_scan(int* __restrict__ cnt, int* __restrict__ rowptr) {
    __shared__ int ssum[1024];
    const int CH = (NN + 1023) / 1024;  // 49
    int t = threadIdx.x;
    int base = t * CH;
    int lim = base < NN ? min(CH, NN - base) : 0;
    int s = 0;
    for (int i = 0; i < lim; i++) s += cnt[base + i];
    ssum[t] = s;
    __syncthreads();
    // Hillis-Steele inclusive scan
    for (int off = 1; off < 1024; off <<= 1) {
        int v = (t >= off) ? ssum[t - off] : 0;
        __syncthreads();
        ssum[t] += v;
        __syncthreads();
    }
    int run = (t == 0) ? 0 : ssum[t - 1];
    for (int i = 0; i < lim; i++) {
        rowptr[base + i] = run;
        run += cnt[base + i];
        cnt[base + i] = 0;  // reset cursor
    }
    if (t == 1023) rowptr[NN] = ssum[1023];
}

__global__ void k_scatter(const int* __restrict__ dst, const int* __restrict__ tsrc,
                          const float* __restrict__ tcoef,
                          const int* __restrict__ rowptr, int* __restrict__ cur,
                          int* __restrict__ esrc, float* __restrict__ ecoef) {
    int e = blockIdx.x * blockDim.x + threadIdx.x;
    if (e >= NE) return;
    int d = dst[e];
    int pos = rowptr[d] + atomicAdd(&cur[d], 1);
    esrc[pos] = tsrc[e];
    ecoef[pos] = tcoef[e];
}

// ---------------- CSR gather aggregation (no atomics) ----------------
// one warp per destination node: acc = dinv^2*h[v] + sum_e coef[e]*h[src[e]]
template <int F>
__global__ void k_gather(const int* __restrict__ rowptr, const int* __restrict__ esrc,
                         const float* __restrict__ ecoef,
                         const float* __restrict__ dinv,
                         const float* __restrict__ h, float* __restrict__ out) {
    int w = (blockIdx.x * blockDim.x + threadIdx.x) >> 5;
    int lane = threadIdx.x & 31;
    if (w >= NN) return;
    constexpr int C = F / 128;  // float4 chunks per lane
    float4 acc[C];
    {
        float s = dinv[w];
        s *= s;
#pragma unroll
        for (int j = 0; j < C; j++) {
            float4 v = *(const float4*)(h + (size_t)w * F + j * 128 + lane * 4);
            acc[j] = make_float4(v.x * s, v.y * s, v.z * s, v.w * s);
        }
    }
    int e = rowptr[w], eEnd = rowptr[w + 1];
    for (; e + 1 < eEnd; e += 2) {  // 2-way unroll for MLP
        int s0 = esrc[e], s1 = esrc[e + 1];
        float c0 = ecoef[e], c1 = ecoef[e + 1];
#pragma unroll
        for (int j = 0; j < C; j++) {
            float4 v0 = *(const float4*)(h + (size_t)s0 * F + j * 128 + lane * 4);
            float4 v1 = *(const float4*)(h + (size_t)s1 * F + j * 128 + lane * 4);
            acc[j].x += v0.x * c0 + v1.x * c1;
            acc[j].y += v0.y * c0 + v1.y * c1;
            acc[j].z += v0.z * c0 + v1.z * c1;
            acc[j].w += v0.w * c0 + v1.w * c1;
        }
    }
    if (e < eEnd) {
        int s0 = esrc[e];
        float c0 = ecoef[e];
#pragma unroll
        for (int j = 0; j < C; j++) {
            float4 v0 = *(const float4*)(h + (size_t)s0 * F + j * 128 + lane * 4);
            acc[j].x += v0.x * c0;
            acc[j].y += v0.y * c0;
            acc[j].z += v0.z * c0;
            acc[j].w += v0.w * c0;
        }
    }
#pragma unroll
    for (int j = 0; j < C; j++)
        *(float4*)(out + (size_t)w * F + j * 128 + lane * 4) = acc[j];
}

// ---------------- TF32 tensor-core GEMM + bias + relu ----------------
__device__ __forceinline__ unsigned f2tf(float x) {
    unsigned u;
    asm("cvt.rna.tf32.f32 %0, %1;" : "=r"(u) : "f"(x));
    return u;
}

__global__ void __launch_bounds__(256)
k_gemm_tf32(const float* __restrict__ A, const float* __restrict__ B,
            const float* __restrict__ bias, float* __restrict__ C,
            int M, int N, int K, int relu) {
    __shared__ float As[128][36];    // [m][k], pad 4
    __shared__ float Bs[32][136];    // [k][n], pad 8

    const int tid = threadIdx.x;
    const int wid = tid >> 5, lane = tid & 31;
    const int g = lane >> 2, t = lane & 3;
    const int wr = (wid >> 2) * 64;
    const int wc = (wid & 3) * 32;
    const int rowBase = blockIdx.y * 128;
    const int colBase = blockIdx.x * 128;

    float acc[4][4][4];
#pragma unroll
    for (int i = 0; i < 4; i++)
#pragma unroll
        for (int j = 0; j < 4; j++)
#pragma unroll
            for (int k = 0; k < 4; k++) acc[i][j][k] = 0.f;

    for (int k0 = 0; k0 < K; k0 += 32) {
#pragma unroll
        for (int i = 0; i < 4; i++) {
            int c = i * 256 + tid;
            int m = c >> 3, kc = (c & 7) * 4;
            int gr = rowBase + m;
            float4 v = (gr < M) ? *(const float4*)(A + (size_t)gr * K + k0 + kc)
                                : make_float4(0.f, 0.f, 0.f, 0.f);
            As[m][kc + 0] = __uint_as_float(f2tf(v.x));
            As[m][kc + 1] = __uint_as_float(f2tf(v.y));
            As[m][kc + 2] = __uint_as_float(f2tf(v.z));
            As[m][kc + 3] = __uint_as_float(f2tf(v.w));
        }
#pragma unroll
        for (int i = 0; i < 4; i++) {
            int c = i * 256 + tid;
            int k = c >> 5, nc = (c & 31) * 4;
            float4 v = *(const float4*)(B + (size_t)(k0 + k) * N + colBase + nc);
            float4 w;
            w.x = __uint_as_float(f2tf(v.x));
            w.y = __uint_as_float(f2tf(v.y));
            w.z = __uint_as_float(f2tf(v.z));
            w.w = __uint_as_float(f2tf(v.w));
            *(float4*)&Bs[k][nc] = w;
        }
        __syncthreads();

#pragma unroll
        for (int kk = 0; kk < 4; kk++) {
            const int kb = kk * 8;
            uint32_t a[4][4], b[4][2];
#pragma unroll
            for (int mi = 0; mi < 4; mi++) {
                int r = wr + mi * 16 + g;
                a[mi][0] = __float_as_uint(As[r][kb + t]);
                a[mi][1] = __float_as_uint(As[r + 8][kb + t]);
                a[mi][2] = __float_as_uint(As[r][kb + t + 4]);
                a[mi][3] = __float_as_uint(As[r + 8][kb + t + 4]);
            }
#pragma unroll
            for (int ni = 0; ni < 4; ni++) {
                int cn = wc + ni * 8 + g;
                b[ni][0] = __float_as_uint(Bs[kb + t][cn]);
                b[ni][1] = __float_as_uint(Bs[kb + t + 4][cn]);
            }
#pragma unroll
            for (int mi = 0; mi < 4; mi++)
#pragma unroll
                for (int ni = 0; ni < 4; ni++) {
                    asm volatile(
                        "mma.sync.aligned.m16n8k8.row.col.f32.tf32.tf32.f32 "
                        "{%0,%1,%2,%3}, {%4,%5,%6,%7}, {%8,%9}, {%0,%1,%2,%3};"
                        : "+f"(acc[mi][ni][0]), "+f"(acc[mi][ni][1]),
                          "+f"(acc[mi][ni][2]), "+f"(acc[mi][ni][3])
                        : "r"(a[mi][0]), "r"(a[mi][1]), "r"(a[mi][2]), "r"(a[mi][3]),
                          "r"(b[ni][0]), "r"(b[ni][1]));
                }
        }
        __syncthreads();
    }

#pragma unroll
    for (int mi = 0; mi < 4; mi++) {
        int r0 = rowBase + wr + mi * 16 + g;
#pragma unroll
        for (int half = 0; half < 2; half++) {
            int r = r0 + half * 8;
            if (r >= M) continue;
#pragma unroll
            for (int ni = 0; ni < 4; ni++) {
                int col = colBase + wc + ni * 8 + 2 * t;
                float v0 = acc[mi][ni][half * 2 + 0] + bias[col];
                float v1 = acc[mi][ni][half * 2 + 1] + bias[col + 1];
                if (relu) {
                    v0 = fmaxf(v0, 0.f);
                    v1 = fmaxf(v1, 0.f);
                }
                *(float2*)(C + (size_t)r * N + col) = make_float2(v0, v1);
            }
        }
    }
}

// ---------------- global max pool (batch is sorted) ----------------
__global__ void k_gstart(const int* __restrict__ batch, int* __restrict__ gstart) {
    int i = blockIdx.x * blockDim.x + threadIdx.x;
    if (i >= NN) return;
    if (i == 0) {
        gstart[0] = 0;
        gstart[NG] = NN;
    } else if (batch[i] != batch[i - 1]) {
        gstart[batch[i]] = i;
    }
}

__global__ void k_pool_max(const float* __restrict__ h, const int* __restrict__ gstart,
                           float* __restrict__ g) {
    int gr = blockIdx.x;
    int f = threadIdx.x;
    int s = gstart[gr], e = gstart[gr + 1];
    float m = -3.4e38f;
    for (int i = s; i < e; i++) m = fmaxf(m, h[(size_t)i * 512 + f]);
    g[gr * 512 + f] = m;
}

// ---------------- launch ----------------
extern "C" void kernel_launch(void* const* d_in, const int* in_sizes, int n_in,
                              void* d_out, int out_size) {
    const float* x   = (const float*)d_in[0];
    const float* ew  = (const float*)d_in[1];
    const float* W1  = (const float*)d_in[2];
    const float* b1  = (const float*)d_in[3];
    const float* W2  = (const float*)d_in[4];
    const float* b2  = (const float*)d_in[5];
    const float* W3  = (const float*)d_in[6];
    const float* b3  = (const float*)d_in[7];
    const float* Wf1 = (const float*)d_in[8];
    const float* bf1 = (const float*)d_in[9];
    const float* Wf2 = (const float*)d_in[10];
    const float* bf2 = (const float*)d_in[11];
    const int* ei    = (const int*)d_in[12];    // int32 (JAX x64 disabled)
    const int* batch = (const int*)d_in[13];    // int32
    float* out = (float*)d_out;

    void *p;
    cudaGetSymbolAddress(&p, g_deg);    float* deg   = (float*)p;
    cudaGetSymbolAddress(&p, g_dinv);   float* dinv  = (float*)p;
    cudaGetSymbolAddress(&p, g_cnt);    int*   cnt   = (int*)p;
    cudaGetSymbolAddress(&p, g_rowptr); int*   rowp  = (int*)p;
    cudaGetSymbolAddress(&p, g_dst);    int*   dst   = (int*)p;
    cudaGetSymbolAddress(&p, g_esrc);   int*   esrc  = (int*)p;
    cudaGetSymbolAddress(&p, g_ecoef);  float* ecoef = (float*)p;
    cudaGetSymbolAddress(&p, g_tsrc);   int*   tsrc  = (int*)p;
    cudaGetSymbolAddress(&p, g_tcoef);  float* tcoef = (float*)p;
    cudaGetSymbolAddress(&p, g_agg);    float* agg   = (float*)p;
    cudaGetSymbolAddress(&p, g_h1);     float* h1    = (float*)p;
    cudaGetSymbolAddress(&p, g_h2);     float* h2    = (float*)p;
    cudaGetSymbolAddress(&p, g_h3);     float* h3    = (float*)p;
    cudaGetSymbolAddress(&p, g_pool);   float* pool  = (float*)p;
    cudaGetSymbolAddress(&p, g_fc1);    float* fc1   = (float*)p;
    cudaGetSymbolAddress(&p, g_gstart); int*   gst   = (int*)p;

    const int T = 256;
    // ---- normalization prep + CSR build ----
    k_deg_init<<<(NN + T - 1) / T, T>>>(deg, cnt);
    k_deg_edges<<<(NE + T - 1) / T, T>>>(ei, ew, deg);
    k_dinv<<<(NN + T - 1) / T, T>>>(deg, dinv);
    k_edge_prep<<<(NE + T - 1) / T, T>>>(ei, ew, dinv, dst, tsrc, tcoef, cnt);
    k_scan<<<1, 1024>>>(cnt, rowp);
    k_scatter<<<(NE + T - 1) / T, T>>>(dst, tsrc, tcoef, rowp, cnt, esrc, ecoef);

    const int MB = (NN + 127) / 128;       // 391 row tiles
    const int GW = (NN * 32 + T - 1) / T;  // gather: warp per node

    // ---- layer 1 ----
    k_gather<128><<<GW, T>>>(rowp, esrc, ecoef, dinv, x, agg);
    k_gemm_tf32<<<dim3(1, MB), 256>>>(agg, W1, b1, h1, NN, 128, 128, 1);

    // ---- layer 2 ----
    k_gather<128><<<GW, T>>>(rowp, esrc, ecoef, dinv, h1, agg);
    k_gemm_tf32<<<dim3(2, MB), 256>>>(agg, W2, b2, h2, NN, 256, 128, 1);

    // ---- layer 3 ----
    k_gather<256><<<GW, T>>>(rowp, esrc, ecoef, dinv, h2, agg);
    k_gemm_tf32<<<dim3(4, MB), 256>>>(agg, W3, b3, h3, NN, 512, 256, 1);

    // ---- global max pool ----
    k_gstart<<<(NN + T - 1) / T, T>>>(batch, gst);
    k_pool_max<<<NG, 512>>>(h3, gst, pool);

    // ---- FC head ----
    k_gemm_tf32<<<dim3(8, 4), 256>>>(pool, Wf1, bf1, fc1, NG, 1024, 512, 1);
    k_gemm_tf32<<<dim3(1, 4), 256>>>(fc1, Wf2, bf2, out, NG, 128, 1024, 0);
}

// round 9
// speedup vs baseline: 1.8722x; 1.0182x over previous
#include <cuda_runtime.h>
#include <cstdint>

#define NN 50000
#define NE 800000
#define NG 512

// ---------------- scratch (float4 => 16B aligned) ----------------
__device__ float  g_deg[NN];
__device__ float  g_dinv[NN];
__device__ int    g_cnt[NN];          // edge counts, reused as scatter cursor
__device__ int    g_rowptr[NN + 1];
__device__ int    g_dst[NE];
__device__ int    g_esrc[NE];         // CSR-sorted src
__device__ float  g_ecoef[NE];        // CSR-sorted coef
__device__ int    g_tsrc[NE];         // unsorted temporaries
__device__ float  g_tcoef[NE];
__device__ float4 g_agg [(size_t)NN * 256 / 4];   // aggregation buffer (max F_in = 256)
__device__ float4 g_h1  [(size_t)NN * 128 / 4];
__device__ float4 g_h2  [(size_t)NN * 256 / 4];
__device__ float4 g_h3  [(size_t)NN * 512 / 4];
__device__ float4 g_pool[NG * 512 / 4];
__device__ float4 g_fc1 [NG * 1024 / 4];
__device__ int    g_gstart[NG + 1];

// ---------------- degree / normalization prep ----------------
__global__ void k_deg_init(float* deg, int* cnt) {
    int i = blockIdx.x * blockDim.x + threadIdx.x;
    if (i < NN) {
        deg[i] = 1.0f;  // self-loop weight
        cnt[i] = 0;
    }
}

__global__ void k_deg_edges(const int* __restrict__ ei,
                            const float* __restrict__ ew, float* deg) {
    int e = blockIdx.x * blockDim.x + threadIdx.x;
    if (e < NE) atomicAdd(&deg[ei[NE + e]], ew[e]);
}

__global__ void k_dinv(const float* __restrict__ deg, float* dinv) {
    int i = blockIdx.x * blockDim.x + threadIdx.x;
    if (i < NN) {
        float d = deg[i];
        dinv[i] = (d > 0.f) ? rsqrtf(d) : 0.f;
    }
}

// coef per edge + per-dst edge count (for CSR)
__global__ void k_edge_prep(const int* __restrict__ ei,
                            const float* __restrict__ ew,
                            const float* __restrict__ dinv,
                            int* __restrict__ dst, int* __restrict__ tsrc,
                            float* __restrict__ tcoef, int* __restrict__ cnt) {
    int e = blockIdx.x * blockDim.x + threadIdx.x;
    if (e >= NE) return;
    int s = ei[e];
    int d = ei[NE + e];
    dst[e] = d;
    tsrc[e] = s;
    tcoef[e] = dinv[s] * ew[e] * dinv[d];
    atomicAdd(&cnt[d], 1);
}

// single-block exclusive scan over cnt[NN] -> rowptr; zeroes cnt for cursor reuse
__global__ void k_scan(int* __restrict__ cnt, int* __restrict__ rowptr) {
    __shared__ int ssum[1024];
    const int CH = (NN + 1023) / 1024;  // 49
    int t = threadIdx.x;
    int base = t * CH;
    int lim = base < NN ? min(CH, NN - base) : 0;
    int s = 0;
    for (int i = 0; i < lim; i++) s += cnt[base + i];
    ssum[t] = s;
    __syncthreads();
    // Hillis-Steele inclusive scan
    for (int off = 1; off < 1024; off <<= 1) {
        int v = (t >= off) ? ssum[t - off] : 0;
        __syncthreads();
        ssum[t] += v;
        __syncthreads();
    }
    int run = (t == 0) ? 0 : ssum[t - 1];
    for (int i = 0; i < lim; i++) {
        rowptr[base + i] = run;
        run += cnt[base + i];
        cnt[base + i] = 0;  // reset cursor
    }
    if (t == 1023) rowptr[NN] = ssum[1023];
}

__global__ void k_scatter(const int* __restrict__ dst, const int* __restrict__ tsrc,
                          const float* __restrict__ tcoef,
                          const int* __restrict__ rowptr, int* __restrict__ cur,
                          int* __restrict__ esrc, float* __restrict__ ecoef) {
    int e = blockIdx.x * blockDim.x + threadIdx.x;
    if (e >= NE) return;
    int d = dst[e];
    int pos = rowptr[d] + atomicAdd(&cur[d], 1);
    esrc[pos] = tsrc[e];
    ecoef[pos] = tcoef[e];
}

// ---------------- CSR gather aggregation (no atomics) ----------------
// one warp per destination node: acc = dinv^2*h[v] + sum_e coef[e]*h[src[e]]
template <int F>
__global__ void k_gather(const int* __restrict__ rowptr, const int* __restrict__ esrc,
                         const float* __restrict__ ecoef,
                         const float* __restrict__ dinv,
                         const float* __restrict__ h, float* __restrict__ out) {
    int w = (blockIdx.x * blockDim.x + threadIdx.x) >> 5;
    int lane = threadIdx.x & 31;
    if (w >= NN) return;
    constexpr int C = F / 128;  // float4 chunks per lane
    float4 acc[C];
    {
        float s = dinv[w];
        s *= s;
#pragma unroll
        for (int j = 0; j < C; j++) {
            float4 v = *(const float4*)(h + (size_t)w * F + j * 128 + lane * 4);
            acc[j] = make_float4(v.x * s, v.y * s, v.z * s, v.w * s);
        }
    }
    int e = rowptr[w], eEnd = rowptr[w + 1];
    // 4-way unroll: 4*C independent loads in flight per lane
    for (; e + 3 < eEnd; e += 4) {
        int s0 = esrc[e], s1 = esrc[e + 1], s2 = esrc[e + 2], s3 = esrc[e + 3];
        float c0 = ecoef[e], c1 = ecoef[e + 1], c2 = ecoef[e + 2], c3 = ecoef[e + 3];
#pragma unroll
        for (int j = 0; j < C; j++) {
            const size_t off = j * 128 + lane * 4;
            float4 v0 = *(const float4*)(h + (size_t)s0 * F + off);
            float4 v1 = *(const float4*)(h + (size_t)s1 * F + off);
            float4 v2 = *(const float4*)(h + (size_t)s2 * F + off);
            float4 v3 = *(const float4*)(h + (size_t)s3 * F + off);
            acc[j].x += v0.x * c0 + v1.x * c1 + v2.x * c2 + v3.x * c3;
            acc[j].y += v0.y * c0 + v1.y * c1 + v2.y * c2 + v3.y * c3;
            acc[j].z += v0.z * c0 + v1.z * c1 + v2.z * c2 + v3.z * c3;
            acc[j].w += v0.w * c0 + v1.w * c1 + v2.w * c2 + v3.w * c3;
        }
    }
    for (; e < eEnd; e++) {
        int s0 = esrc[e];
        float c0 = ecoef[e];
#pragma unroll
        for (int j = 0; j < C; j++) {
            float4 v0 = *(const float4*)(h + (size_t)s0 * F + j * 128 + lane * 4);
            acc[j].x += v0.x * c0;
            acc[j].y += v0.y * c0;
            acc[j].z += v0.z * c0;
            acc[j].w += v0.w * c0;
        }
    }
#pragma unroll
    for (int j = 0; j < C; j++)
        *(float4*)(out + (size_t)w * F + j * 128 + lane * 4) = acc[j];
}

// ---------------- TF32 tensor-core GEMM + bias + relu (register-prefetch pipeline) ----------------
__device__ __forceinline__ unsigned f2tf(float x) {
    unsigned u;
    asm("cvt.rna.tf32.f32 %0, %1;" : "=r"(u) : "f"(x));
    return u;
}

__global__ void __launch_bounds__(256)
k_gemm_tf32(const float* __restrict__ A, const float* __restrict__ B,
            const float* __restrict__ bias, float* __restrict__ C,
            int M, int N, int K, int relu) {
    __shared__ float As[128][36];    // [m][k], pad 4
    __shared__ float Bs[32][136];    // [k][n], pad 8

    const int tid = threadIdx.x;
    const int wid = tid >> 5, lane = tid & 31;
    const int g = lane >> 2, t = lane & 3;
    const int wr = (wid >> 2) * 64;
    const int wc = (wid & 3) * 32;
    const int rowBase = blockIdx.y * 128;
    const int colBase = blockIdx.x * 128;

    float4 pa[4], pb[4];

    auto loadA = [&](int k0, int i) -> float4 {
        int c = i * 256 + tid;
        int m = c >> 3, kc = (c & 7) * 4;
        int gr = rowBase + m;
        return (gr < M) ? *(const float4*)(A + (size_t)gr * K + k0 + kc)
                        : make_float4(0.f, 0.f, 0.f, 0.f);
    };
    auto loadB = [&](int k0, int i) -> float4 {
        int c = i * 256 + tid;
        int k = c >> 5, nc = (c & 31) * 4;
        return *(const float4*)(B + (size_t)(k0 + k) * N + colBase + nc);
    };
    auto stTiles = [&]() {
#pragma unroll
        for (int i = 0; i < 4; i++) {
            int c = i * 256 + tid;
            int m = c >> 3, kc = (c & 7) * 4;
            As[m][kc + 0] = __uint_as_float(f2tf(pa[i].x));
            As[m][kc + 1] = __uint_as_float(f2tf(pa[i].y));
            As[m][kc + 2] = __uint_as_float(f2tf(pa[i].z));
            As[m][kc + 3] = __uint_as_float(f2tf(pa[i].w));
        }
#pragma unroll
        for (int i = 0; i < 4; i++) {
            int c = i * 256 + tid;
            int k = c >> 5, nc = (c & 31) * 4;
            float4 w;
            w.x = __uint_as_float(f2tf(pb[i].x));
            w.y = __uint_as_float(f2tf(pb[i].y));
            w.z = __uint_as_float(f2tf(pb[i].z));
            w.w = __uint_as_float(f2tf(pb[i].w));
            *(float4*)&Bs[k][nc] = w;
        }
    };

    float acc[4][4][4];
#pragma unroll
    for (int i = 0; i < 4; i++)
#pragma unroll
        for (int j = 0; j < 4; j++)
#pragma unroll
            for (int k = 0; k < 4; k++) acc[i][j][k] = 0.f;

    // prologue: tile 0
#pragma unroll
    for (int i = 0; i < 4; i++) pa[i] = loadA(0, i);
#pragma unroll
    for (int i = 0; i < 4; i++) pb[i] = loadB(0, i);
    stTiles();
    __syncthreads();

    for (int k0 = 0; k0 < K; k0 += 32) {
        const bool next = (k0 + 32) < K;
        // issue next tile's global loads; latency hides behind the MMA loop
        if (next) {
#pragma unroll
            for (int i = 0; i < 4; i++) pa[i] = loadA(k0 + 32, i);
#pragma unroll
            for (int i = 0; i < 4; i++) pb[i] = loadB(k0 + 32, i);
        }

#pragma unroll
        for (int kk = 0; kk < 4; kk++) {
            const int kb = kk * 8;
            uint32_t a[4][4], b[4][2];
#pragma unroll
            for (int mi = 0; mi < 4; mi++) {
                int r = wr + mi * 16 + g;
                a[mi][0] = __float_as_uint(As[r][kb + t]);
                a[mi][1] = __float_as_uint(As[r + 8][kb + t]);
                a[mi][2] = __float_as_uint(As[r][kb + t + 4]);
                a[mi][3] = __float_as_uint(As[r + 8][kb + t + 4]);
            }
#pragma unroll
            for (int ni = 0; ni < 4; ni++) {
                int cn = wc + ni * 8 + g;
                b[ni][0] = __float_as_uint(Bs[kb + t][cn]);
                b[ni][1] = __float_as_uint(Bs[kb + t + 4][cn]);
            }
#pragma unroll
            for (int mi = 0; mi < 4; mi++)
#pragma unroll
                for (int ni = 0; ni < 4; ni++) {
                    asm volatile(
                        "mma.sync.aligned.m16n8k8.row.col.f32.tf32.tf32.f32 "
                        "{%0,%1,%2,%3}, {%4,%5,%6,%7}, {%8,%9}, {%0,%1,%2,%3};"
                        : "+f"(acc[mi][ni][0]), "+f"(acc[mi][ni][1]),
                          "+f"(acc[mi][ni][2]), "+f"(acc[mi][ni][3])
                        : "r"(a[mi][0]), "r"(a[mi][1]), "r"(a[mi][2]), "r"(a[mi][3]),
                          "r"(b[ni][0]), "r"(b[ni][1]));
                }
        }
        __syncthreads();   // all warps done reading smem
        if (next) {
            stTiles();
            __syncthreads();
        }
    }

#pragma unroll
    for (int mi = 0; mi < 4; mi++) {
        int r0 = rowBase + wr + mi * 16 + g;
#pragma unroll
        for (int half = 0; half < 2; half++) {
            int r = r0 + half * 8;
            if (r >= M) continue;
#pragma unroll
            for (int ni = 0; ni < 4; ni++) {
                int col = colBase + wc + ni * 8 + 2 * t;
                float v0 = acc[mi][ni][half * 2 + 0] + bias[col];
                float v1 = acc[mi][ni][half * 2 + 1] + bias[col + 1];
                if (relu) {
                    v0 = fmaxf(v0, 0.f);
                    v1 = fmaxf(v1, 0.f);
                }
                *(float2*)(C + (size_t)r * N + col) = make_float2(v0, v1);
            }
        }
    }
}

// ---------------- global max pool (batch is sorted) ----------------
__global__ void k_gstart(const int* __restrict__ batch, int* __restrict__ gstart) {
    int i = blockIdx.x * blockDim.x + threadIdx.x;
    if (i >= NN) return;
    if (i == 0) {
        gstart[0] = 0;
        gstart[NG] = NN;
    } else if (batch[i] != batch[i - 1]) {
        gstart[batch[i]] = i;
    }
}

__global__ void k_pool_max(const float* __restrict__ h, const int* __restrict__ gstart,
                           float* __restrict__ g) {
    int gr = blockIdx.x;
    int f = threadIdx.x;
    int s = gstart[gr], e = gstart[gr + 1];
    float m = -3.4e38f;
    for (int i = s; i < e; i++) m = fmaxf(m, h[(size_t)i * 512 + f]);
    g[gr * 512 + f] = m;
}

// ---------------- launch ----------------
extern "C" void kernel_launch(void* const* d_in, const int* in_sizes, int n_in,
                              void* d_out, int out_size) {
    const float* x   = (const float*)d_in[0];
    const float* ew  = (const float*)d_in[1];
    const float* W1  = (const float*)d_in[2];
    const float* b1  = (const float*)d_in[3];
    const float* W2  = (const float*)d_in[4];
    const float* b2  = (const float*)d_in[5];
    const float* W3  = (const float*)d_in[6];
    const float* b3  = (const float*)d_in[7];
    const float* Wf1 = (const float*)d_in[8];
    const float* bf1 = (const float*)d_in[9];
    const float* Wf2 = (const float*)d_in[10];
    const float* bf2 = (const float*)d_in[11];
    const int* ei    = (const int*)d_in[12];    // int32 (JAX x64 disabled)
    const int* batch = (const int*)d_in[13];    // int32
    float* out = (float*)d_out;

    void *p;
    cudaGetSymbolAddress(&p, g_deg);    float* deg   = (float*)p;
    cudaGetSymbolAddress(&p, g_dinv);   float* dinv  = (float*)p;
    cudaGetSymbolAddress(&p, g_cnt);    int*   cnt   = (int*)p;
    cudaGetSymbolAddress(&p, g_rowptr); int*   rowp  = (int*)p;
    cudaGetSymbolAddress(&p, g_dst);    int*   dst   = (int*)p;
    cudaGetSymbolAddress(&p, g_esrc);   int*   esrc  = (int*)p;
    cudaGetSymbolAddress(&p, g_ecoef);  float* ecoef = (float*)p;
    cudaGetSymbolAddress(&p, g_tsrc);   int*   tsrc  = (int*)p;
    cudaGetSymbolAddress(&p, g_tcoef);  float* tcoef = (float*)p;
    cudaGetSymbolAddress(&p, g_agg);    float* agg   = (float*)p;
    cudaGetSymbolAddress(&p, g_h1);     float* h1    = (float*)p;
    cudaGetSymbolAddress(&p, g_h2);     float* h2    = (float*)p;
    cudaGetSymbolAddress(&p, g_h3);     float* h3    = (float*)p;
    cudaGetSymbolAddress(&p, g_pool);   float* pool  = (float*)p;
    cudaGetSymbolAddress(&p, g_fc1);    float* fc1   = (float*)p;
    cudaGetSymbolAddress(&p, g_gstart); int*   gst   = (int*)p;

    const int T = 256;
    // ---- normalization prep + CSR build ----
    k_deg_init<<<(NN + T - 1) / T, T>>>(deg, cnt);
    k_deg_edges<<<(NE + T - 1) / T, T>>>(ei, ew, deg);
    k_dinv<<<(NN + T - 1) / T, T>>>(deg, dinv);
    k_edge_prep<<<(NE + T - 1) / T, T>>>(ei, ew, dinv, dst, tsrc, tcoef, cnt);
    k_scan<<<1, 1024>>>(cnt, rowp);
    k_scatter<<<(NE + T - 1) / T, T>>>(dst, tsrc, tcoef, rowp, cnt, esrc, ecoef);

    const int MB = (NN + 127) / 128;       // 391 row tiles
    const int GW = (NN * 32 + T - 1) / T;  // gather: warp per node

    // ---- layer 1 ----
    k_gather<128><<<GW, T>>>(rowp, esrc, ecoef, dinv, x, agg);
    k_gemm_tf32<<<dim3(1, MB), 256>>>(agg, W1, b1, h1, NN, 128, 128, 1);

    // ---- layer 2 ----
    k_gather<128><<<GW, T>>>(rowp, esrc, ecoef, dinv, h1, agg);
    k_gemm_tf32<<<dim3(2, MB), 256>>>(agg, W2, b2, h2, NN, 256, 128, 1);

    // ---- layer 3 ----
    k_gather<256><<<GW, T>>>(rowp, esrc, ecoef, dinv, h2, agg);
    k_gemm_tf32<<<dim3(4, MB), 256>>>(agg, W3, b3, h3, NN, 512, 256, 1);

    // ---- global max pool ----
    k_gstart<<<(NN + T - 1) / T, T>>>(batch, gst);
    k_pool_max<<<NG, 512>>>(h3, gst, pool);

    // ---- FC head ----
    k_gemm_tf32<<<dim3(8, 4), 256>>>(pool, Wf1, bf1, fc1, NG, 1024, 512, 1);
    k_gemm_tf32<<<dim3(1, 4), 256>>>(fc1, Wf2, bf2, out, NG, 128, 1024, 0);
}

// round 11
// speedup vs baseline: 1.9262x; 1.0288x over previous
#include <cuda_runtime.h>
#include <cstdint>

#define NN 50000
#define NE 800000
#define NG 512

// ---------------- scratch (float4 => 16B aligned) ----------------
__device__ float  g_deg[NN];
__device__ float  g_dinv[NN];
__device__ int    g_cnt[NN];          // edge counts, reused as scatter cursor
__device__ int    g_rowptr[NN + 1];
__device__ int    g_esrc[NE];         // CSR-sorted src
__device__ float  g_ecoef[NE];        // CSR-sorted coef
__device__ float4 g_agg [(size_t)NN * 256 / 4];
__device__ float4 g_h1  [(size_t)NN * 128 / 4];
__device__ float4 g_h2  [(size_t)NN * 256 / 4];
__device__ float4 g_h3  [(size_t)NN * 512 / 4];
__device__ float4 g_pool[NG * 512 / 4];
__device__ float4 g_fc1 [NG * 1024 / 4];
__device__ int    g_gstart[NG + 1];

// ---------------- degree / count prep ----------------
__global__ void k_deg_init(float* deg, int* cnt) {
    int i = blockIdx.x * blockDim.x + threadIdx.x;
    if (i < NN) {
        deg[i] = 1.0f;  // self-loop weight
        cnt[i] = 0;
    }
}

// fused: weighted degree + edge count per destination
__global__ void k_deg_edges(const int* __restrict__ ei,
                            const float* __restrict__ ew,
                            float* deg, int* cnt) {
    int e = blockIdx.x * blockDim.x + threadIdx.x;
    if (e >= NE) return;
    int d = ei[NE + e];
    atomicAdd(&deg[d], ew[e]);
    atomicAdd(&cnt[d], 1);
}

__global__ void k_dinv(const float* __restrict__ deg, float* dinv) {
    int i = blockIdx.x * blockDim.x + threadIdx.x;
    if (i < NN) {
        float d = deg[i];
        dinv[i] = (d > 0.f) ? rsqrtf(d) : 0.f;
    }
}

// single-block exclusive scan over cnt[NN] -> rowptr; zeroes cnt for cursor reuse
__global__ void k_scan(int* __restrict__ cnt, int* __restrict__ rowptr) {
    __shared__ int ssum[1024];
    const int CH = (NN + 1023) / 1024;  // 49
    int t = threadIdx.x;
    int base = t * CH;
    int lim = base < NN ? min(CH, NN - base) : 0;
    int s = 0;
    for (int i = 0; i < lim; i++) s += cnt[base + i];
    ssum[t] = s;
    __syncthreads();
    for (int off = 1; off < 1024; off <<= 1) {
        int v = (t >= off) ? ssum[t - off] : 0;
        __syncthreads();
        ssum[t] += v;
        __syncthreads();
    }
    int run = (t == 0) ? 0 : ssum[t - 1];
    for (int i = 0; i < lim; i++) {
        rowptr[base + i] = run;
        run += cnt[base + i];
        cnt[base + i] = 0;  // reset cursor
    }
    if (t == 1023) rowptr[NN] = ssum[1023];
}

// fused: compute coef + scatter into CSR slots (no temp arrays)
__global__ void k_edge_scatter(const int* __restrict__ ei,
                               const float* __restrict__ ew,
                               const float* __restrict__ dinv,
                               const int* __restrict__ rowptr, int* __restrict__ cur,
                               int* __restrict__ esrc, float* __restrict__ ecoef) {
    int e = blockIdx.x * blockDim.x + threadIdx.x;
    if (e >= NE) return;
    int s = ei[e];
    int d = ei[NE + e];
    int pos = rowptr[d] + atomicAdd(&cur[d], 1);
    esrc[pos] = s;
    ecoef[pos] = dinv[s] * ew[e] * dinv[d];
}

// ---------------- CSR gather aggregation (no atomics) ----------------
template <int F>
__global__ void k_gather(const int* __restrict__ rowptr, const int* __restrict__ esrc,
                         const float* __restrict__ ecoef, const float* __restrict__ dinv,
                         const float* __restrict__ h, float* __restrict__ out) {
    int w = (blockIdx.x * blockDim.x + threadIdx.x) >> 5;
    int lane = threadIdx.x & 31;
    if (w >= NN) return;
    constexpr int C = F / 128;
    float4 acc[C];
    {
        float s = dinv[w];
        s *= s;
#pragma unroll
        for (int j = 0; j < C; j++) {
            float4 v = *(const float4*)(h + (size_t)w * F + j * 128 + lane * 4);
            acc[j] = make_float4(v.x * s, v.y * s, v.z * s, v.w * s);
        }
    }
    int e = rowptr[w], eEnd = rowptr[w + 1];
    for (; e + 3 < eEnd; e += 4) {
        int s0 = esrc[e], s1 = esrc[e + 1], s2 = esrc[e + 2], s3 = esrc[e + 3];
        float c0 = ecoef[e], c1 = ecoef[e + 1], c2 = ecoef[e + 2], c3 = ecoef[e + 3];
#pragma unroll
        for (int j = 0; j < C; j++) {
            const size_t off = j * 128 + lane * 4;
            float4 v0 = *(const float4*)(h + (size_t)s0 * F + off);
            float4 v1 = *(const float4*)(h + (size_t)s1 * F + off);
            float4 v2 = *(const float4*)(h + (size_t)s2 * F + off);
            float4 v3 = *(const float4*)(h + (size_t)s3 * F + off);
            acc[j].x += v0.x * c0 + v1.x * c1 + v2.x * c2 + v3.x * c3;
            acc[j].y += v0.y * c0 + v1.y * c1 + v2.y * c2 + v3.y * c3;
            acc[j].z += v0.z * c0 + v1.z * c1 + v2.z * c2 + v3.z * c3;
            acc[j].w += v0.w * c0 + v1.w * c1 + v2.w * c2 + v3.w * c3;
        }
    }
    for (; e < eEnd; e++) {
        int s0 = esrc[e];
        float c0 = ecoef[e];
#pragma unroll
        for (int j = 0; j < C; j++) {
            float4 v0 = *(const float4*)(h + (size_t)s0 * F + j * 128 + lane * 4);
            acc[j].x += v0.x * c0;
            acc[j].y += v0.y * c0;
            acc[j].z += v0.z * c0;
            acc[j].w += v0.w * c0;
        }
    }
#pragma unroll
    for (int j = 0; j < C; j++)
        *(float4*)(out + (size_t)w * F + j * 128 + lane * 4) = acc[j];
}

// ---------------- TF32 mma GEMM + bias + relu ----------------
// Block 128x128, BK=32, 128 threads = 4 warps, warp tile 64x64 (2x2 warp grid).
// LDS per warp per kk: 16 A + 16 B for 32 MMAs (0.5 ratio vs 1.5 at 64x32).
__device__ __forceinline__ unsigned f2tf(float x) {
    unsigned u;
    asm("cvt.rna.tf32.f32 %0, %1;" : "=r"(u) : "f"(x));
    return u;
}

__global__ void __launch_bounds__(128)
k_gemm_tf32(const float* __restrict__ A, const float* __restrict__ B,
            const float* __restrict__ bias, float* __restrict__ C,
            int M, int N, int K, int relu) {
    __shared__ float As[128][36];    // [m][k], pad 4: frag bank = 4g+t (conflict-free)
    __shared__ float Bs[32][136];    // [k][n], pad 8: frag bank = 8t+g (conflict-free)

    const int tid = threadIdx.x;
    const int wid = tid >> 5, lane = tid & 31;
    const int g = lane >> 2, t = lane & 3;
    const int wr = (wid >> 1) * 64;      // warp row: 0/64
    const int wc = (wid & 1) * 64;       // warp col: 0/64
    const int rowBase = blockIdx.y * 128;
    const int colBase = blockIdx.x * 128;

    float acc[4][8][4];
#pragma unroll
    for (int i = 0; i < 4; i++)
#pragma unroll
        for (int j = 0; j < 8; j++)
#pragma unroll
            for (int k = 0; k < 4; k++) acc[i][j][k] = 0.f;

    for (int k0 = 0; k0 < K; k0 += 32) {
        // A tile: 1024 float4 / 128 threads = 8 each
#pragma unroll
        for (int i = 0; i < 8; i++) {
            int c = i * 128 + tid;
            int m = c >> 3, kc = (c & 7) * 4;
            int gr = rowBase + m;
            float4 v = (gr < M) ? *(const float4*)(A + (size_t)gr * K + k0 + kc)
                                : make_float4(0.f, 0.f, 0.f, 0.f);
            As[m][kc + 0] = __uint_as_float(f2tf(v.x));
            As[m][kc + 1] = __uint_as_float(f2tf(v.y));
            As[m][kc + 2] = __uint_as_float(f2tf(v.z));
            As[m][kc + 3] = __uint_as_float(f2tf(v.w));
        }
        // B tile
#pragma unroll
        for (int i = 0; i < 8; i++) {
            int c = i * 128 + tid;
            int k = c >> 5, nc = (c & 31) * 4;
            float4 v = *(const float4*)(B + (size_t)(k0 + k) * N + colBase + nc);
            float4 w;
            w.x = __uint_as_float(f2tf(v.x));
            w.y = __uint_as_float(f2tf(v.y));
            w.z = __uint_as_float(f2tf(v.z));
            w.w = __uint_as_float(f2tf(v.w));
            *(float4*)&Bs[k][nc] = w;
        }
        __syncthreads();

#pragma unroll
        for (int kk = 0; kk < 4; kk++) {
            const int kb = kk * 8;
            uint32_t a[4][4], b[8][2];
#pragma unroll
            for (int mi = 0; mi < 4; mi++) {
                int r = wr + mi * 16 + g;
                a[mi][0] = __float_as_uint(As[r][kb + t]);
                a[mi][1] = __float_as_uint(As[r + 8][kb + t]);
                a[mi][2] = __float_as_uint(As[r][kb + t + 4]);
                a[mi][3] = __float_as_uint(As[r + 8][kb + t + 4]);
            }
#pragma unroll
            for (int ni = 0; ni < 8; ni++) {
                int cn = wc + ni * 8 + g;
                b[ni][0] = __float_as_uint(Bs[kb + t][cn]);
                b[ni][1] = __float_as_uint(Bs[kb + t + 4][cn]);
            }
#pragma unroll
            for (int mi = 0; mi < 4; mi++)
#pragma unroll
                for (int ni = 0; ni < 8; ni++) {
                    asm volatile(
                        "mma.sync.aligned.m16n8k8.row.col.f32.tf32.tf32.f32 "
                        "{%0,%1,%2,%3}, {%4,%5,%6,%7}, {%8,%9}, {%0,%1,%2,%3};"
                        : "+f"(acc[mi][ni][0]), "+f"(acc[mi][ni][1]),
                          "+f"(acc[mi][ni][2]), "+f"(acc[mi][ni][3])
                        : "r"(a[mi][0]), "r"(a[mi][1]), "r"(a[mi][2]), "r"(a[mi][3]),
                          "r"(b[ni][0]), "r"(b[ni][1]));
                }
        }
        __syncthreads();
    }

#pragma unroll
    for (int mi = 0; mi < 4; mi++) {
        int r0 = rowBase + wr + mi * 16 + g;
#pragma unroll
        for (int half = 0; half < 2; half++) {
            int r = r0 + half * 8;
            if (r >= M) continue;
#pragma unroll
            for (int ni = 0; ni < 8; ni++) {
                int col = colBase + wc + ni * 8 + 2 * t;
                float v0 = acc[mi][ni][half * 2 + 0] + bias[col];
                float v1 = acc[mi][ni][half * 2 + 1] + bias[col + 1];
                if (relu) {
                    v0 = fmaxf(v0, 0.f);
                    v1 = fmaxf(v1, 0.f);
                }
                *(float2*)(C + (size_t)r * N + col) = make_float2(v0, v1);
            }
        }
    }
}

// ---------------- global max pool (batch is sorted) ----------------
__global__ void k_gstart(const int* __restrict__ batch, int* __restrict__ gstart) {
    int i = blockIdx.x * blockDim.x + threadIdx.x;
    if (i >= NN) return;
    if (i == 0) {
        gstart[0] = 0;
        gstart[NG] = NN;
    } else if (batch[i] != batch[i - 1]) {
        gstart[batch[i]] = i;
    }
}

__global__ void k_pool_max(const float* __restrict__ h, const int* __restrict__ gstart,
                           float* __restrict__ g) {
    int gr = blockIdx.x;
    int f = threadIdx.x;
    int s = gstart[gr], e = gstart[gr + 1];
    float m = -3.4e38f;
    for (int i = s; i < e; i++) m = fmaxf(m, h[(size_t)i * 512 + f]);
    g[gr * 512 + f] = m;
}

// ---------------- launch ----------------
extern "C" void kernel_launch(void* const* d_in, const int* in_sizes, int n_in,
                              void* d_out, int out_size) {
    const float* x   = (const float*)d_in[0];
    const float* ew  = (const float*)d_in[1];
    const float* W1  = (const float*)d_in[2];
    const float* b1  = (const float*)d_in[3];
    const float* W2  = (const float*)d_in[4];
    const float* b2  = (const float*)d_in[5];
    const float* W3  = (const float*)d_in[6];
    const float* b3  = (const float*)d_in[7];
    const float* Wf1 = (const float*)d_in[8];
    const float* bf1 = (const float*)d_in[9];
    const float* Wf2 = (const float*)d_in[10];
    const float* bf2 = (const float*)d_in[11];
    const int* ei    = (const int*)d_in[12];    // int32 (JAX x64 disabled)
    const int* batch = (const int*)d_in[13];    // int32
    float* out = (float*)d_out;

    void *p;
    cudaGetSymbolAddress(&p, g_deg);    float* deg   = (float*)p;
    cudaGetSymbolAddress(&p, g_dinv);   float* dinv  = (float*)p;
    cudaGetSymbolAddress(&p, g_cnt);    int*   cnt   = (int*)p;
    cudaGetSymbolAddress(&p, g_rowptr); int*   rowp  = (int*)p;
    cudaGetSymbolAddress(&p, g_esrc);   int*   esrc  = (int*)p;
    cudaGetSymbolAddress(&p, g_ecoef);  float* ecoef = (float*)p;
    cudaGetSymbolAddress(&p, g_agg);    float* agg   = (float*)p;
    cudaGetSymbolAddress(&p, g_h1);     float* h1    = (float*)p;
    cudaGetSymbolAddress(&p, g_h2);     float* h2    = (float*)p;
    cudaGetSymbolAddress(&p, g_h3);     float* h3    = (float*)p;
    cudaGetSymbolAddress(&p, g_pool);   float* pool  = (float*)p;
    cudaGetSymbolAddress(&p, g_fc1);    float* fc1   = (float*)p;
    cudaGetSymbolAddress(&p, g_gstart); int*   gst   = (int*)p;

    const int T = 256;
    // ---- normalization prep + CSR build (fused, 5 kernels) ----
    k_deg_init<<<(NN + T - 1) / T, T>>>(deg, cnt);
    k_deg_edges<<<(NE + T - 1) / T, T>>>(ei, ew, deg, cnt);
    k_dinv<<<(NN + T - 1) / T, T>>>(deg, dinv);
    k_scan<<<1, 1024>>>(cnt, rowp);
    k_edge_scatter<<<(NE + T - 1) / T, T>>>(ei, ew, dinv, rowp, cnt, esrc, ecoef);

    const int MB = (NN + 127) / 128;       // 391 row tiles
    const int GW = (NN * 32 + T - 1) / T;  // gather: warp per node

    // ---- layer 1 ----
    k_gather<128><<<GW, T>>>(rowp, esrc, ecoef, dinv, x, agg);
    k_gemm_tf32<<<dim3(1, MB), 128>>>(agg, W1, b1, h1, NN, 128, 128, 1);

    // ---- layer 2 ----
    k_gather<128><<<GW, T>>>(rowp, esrc, ecoef, dinv, h1, agg);
    k_gemm_tf32<<<dim3(2, MB), 128>>>(agg, W2, b2, h2, NN, 256, 128, 1);

    // ---- layer 3 ----
    k_gather<256><<<GW, T>>>(rowp, esrc, ecoef, dinv, h2, agg);
    k_gemm_tf32<<<dim3(4, MB), 128>>>(agg, W3, b3, h3, NN, 512, 256, 1);

    // ---- global max pool ----
    k_gstart<<<(NN + T - 1) / T, T>>>(batch, gst);
    k_pool_max<<<NG, 512>>>(h3, gst, pool);

    // ---- FC head ----
    k_gemm_tf32<<<dim3(8, 4), 128>>>(pool, Wf1, bf1, fc1, NG, 1024, 512, 1);
    k_gemm_tf32<<<dim3(1, 4), 128>>>(fc1, Wf2, bf2, out, NG, 128, 1024, 0);
}

// round 14
// speedup vs baseline: 2.2528x; 1.1695x over previous
#include <cuda_runtime.h>
#include <cstdint>

#define NN 50000
#define NE 800000
#define NG 512

#define SCAN_B 256
#define SCAN_CH 196   // 256*196 = 50176 >= NN

// ---------------- scratch (float4 => 16B aligned) ----------------
__device__ float  g_deg[NN];
__device__ float  g_dinv[NN];
__device__ int    g_cnt[NN];          // edge counts, reused as scatter cursor
__device__ int    g_rowptr[NN + 1];
__device__ int    g_part[SCAN_B];
__device__ int    g_esrc[NE];         // CSR-sorted src
__device__ float  g_ecoef[NE];        // CSR-sorted coef
__device__ float4 g_agg [(size_t)NN * 256 / 4];
__device__ float4 g_h1  [(size_t)NN * 128 / 4];
__device__ float4 g_h2  [(size_t)NN * 256 / 4];
__device__ float4 g_h3  [(size_t)NN * 512 / 4];
__device__ float4 g_pool[NG * 512 / 4];
__device__ float4 g_fc1 [NG * 1024 / 4];
__device__ int    g_gstart[NG + 1];

// ---------------- degree / count prep ----------------
__global__ void k_deg_init(float* deg, int* cnt) {
    int i = blockIdx.x * blockDim.x + threadIdx.x;
    if (i < NN) {
        deg[i] = 1.0f;  // self-loop weight
        cnt[i] = 0;
    }
}

// fused: weighted degree + edge count per destination
__global__ void k_deg_edges(const int* __restrict__ ei,
                            const float* __restrict__ ew,
                            float* deg, int* cnt) {
    int e = blockIdx.x * blockDim.x + threadIdx.x;
    if (e >= NE) return;
    int d = ei[NE + e];
    atomicAdd(&deg[d], ew[e]);
    atomicAdd(&cnt[d], 1);
}

__global__ void k_dinv(const float* __restrict__ deg, float* dinv) {
    int i = blockIdx.x * blockDim.x + threadIdx.x;
    if (i < NN) {
        float d = deg[i];
        dinv[i] = (d > 0.f) ? rsqrtf(d) : 0.f;
    }
}

// ---------------- 3-phase parallel exclusive scan ----------------
// phase 1: per-block chunk sums
__global__ void k_scan_part(const int* __restrict__ cnt, int* __restrict__ part) {
    __shared__ int s[256];
    int b = blockIdx.x, t = threadIdx.x;
    int idx = b * SCAN_CH + t;
    s[t] = (t < SCAN_CH && idx < NN) ? cnt[idx] : 0;
    __syncthreads();
    for (int off = 128; off > 0; off >>= 1) {
        if (t < off) s[t] += s[t + off];
        __syncthreads();
    }
    if (t == 0) part[b] = s[0];
}

// phase 2: exclusive scan of the 256 block sums (single block)
__global__ void k_scan_top(int* __restrict__ part, int* __restrict__ rowptr) {
    __shared__ int s[SCAN_B];
    int t = threadIdx.x;
    int v = part[t];
    s[t] = v;
    __syncthreads();
    for (int off = 1; off < SCAN_B; off <<= 1) {
        int u = (t >= off) ? s[t - off] : 0;
        __syncthreads();
        s[t] += u;
        __syncthreads();
    }
    part[t] = s[t] - v;  // exclusive
    if (t == SCAN_B - 1) rowptr[NN] = s[t];
}

// phase 3: per-block local exclusive scan + global offset; zero cnt for cursor
__global__ void k_scan_fin(int* __restrict__ cnt, const int* __restrict__ part,
                           int* __restrict__ rowptr) {
    __shared__ int s[256];
    int b = blockIdx.x, t = threadIdx.x;
    int idx = b * SCAN_CH + t;
    int v = (t < SCAN_CH && idx < NN) ? cnt[idx] : 0;
    s[t] = v;
    __syncthreads();
    for (int off = 1; off < 256; off <<= 1) {
        int u = (t >= off) ? s[t - off] : 0;
        __syncthreads();
        s[t] += u;
        __syncthreads();
    }
    if (t < SCAN_CH && idx < NN) {
        rowptr[idx] = part[b] + s[t] - v;  // exclusive
        cnt[idx] = 0;                       // reset cursor
    }
}

// fused: compute coef + scatter into CSR slots (no temp arrays)
__global__ void k_edge_scatter(const int* __restrict__ ei,
                               const float* __restrict__ ew,
                               const float* __restrict__ dinv,
                               const int* __restrict__ rowptr, int* __restrict__ cur,
                               int* __restrict__ esrc, float* __restrict__ ecoef) {
    int e = blockIdx.x * blockDim.x + threadIdx.x;
    if (e >= NE) return;
    int s = ei[e];
    int d = ei[NE + e];
    int pos = rowptr[d] + atomicAdd(&cur[d], 1);
    esrc[pos] = s;
    ecoef[pos] = dinv[s] * ew[e] * dinv[d];
}

// ---------------- CSR gather aggregation (no atomics) ----------------
template <int F>
__global__ void k_gather(const int* __restrict__ rowptr, const int* __restrict__ esrc,
                         const float* __restrict__ ecoef, const float* __restrict__ dinv,
                         const float* __restrict__ h, float* __restrict__ out) {
    int w = (blockIdx.x * blockDim.x + threadIdx.x) >> 5;
    int lane = threadIdx.x & 31;
    if (w >= NN) return;
    constexpr int C = F / 128;
    float4 acc[C];
    {
        float s = dinv[w];
        s *= s;
#pragma unroll
        for (int j = 0; j < C; j++) {
            float4 v = *(const float4*)(h + (size_t)w * F + j * 128 + lane * 4);
            acc[j] = make_float4(v.x * s, v.y * s, v.z * s, v.w * s);
        }
    }
    int e = rowptr[w], eEnd = rowptr[w + 1];
    for (; e + 3 < eEnd; e += 4) {
        int s0 = esrc[e], s1 = esrc[e + 1], s2 = esrc[e + 2], s3 = esrc[e + 3];
        float c0 = ecoef[e], c1 = ecoef[e + 1], c2 = ecoef[e + 2], c3 = ecoef[e + 3];
#pragma unroll
        for (int j = 0; j < C; j++) {
            const size_t off = j * 128 + lane * 4;
            float4 v0 = *(const float4*)(h + (size_t)s0 * F + off);
            float4 v1 = *(const float4*)(h + (size_t)s1 * F + off);
            float4 v2 = *(const float4*)(h + (size_t)s2 * F + off);
            float4 v3 = *(const float4*)(h + (size_t)s3 * F + off);
            acc[j].x += v0.x * c0 + v1.x * c1 + v2.x * c2 + v3.x * c3;
            acc[j].y += v0.y * c0 + v1.y * c1 + v2.y * c2 + v3.y * c3;
            acc[j].z += v0.z * c0 + v1.z * c1 + v2.z * c2 + v3.z * c3;
            acc[j].w += v0.w * c0 + v1.w * c1 + v2.w * c2 + v3.w * c3;
        }
    }
    for (; e < eEnd; e++) {
        int s0 = esrc[e];
        float c0 = ecoef[e];
#pragma unroll
        for (int j = 0; j < C; j++) {
            float4 v0 = *(const float4*)(h + (size_t)s0 * F + j * 128 + lane * 4);
            acc[j].x += v0.x * c0;
            acc[j].y += v0.y * c0;
            acc[j].z += v0.z * c0;
            acc[j].w += v0.w * c0;
        }
    }
#pragma unroll
    for (int j = 0; j < C; j++)
        *(float4*)(out + (size_t)w * F + j * 128 + lane * 4) = acc[j];
}

// ---------------- TF32 mma GEMM + bias + relu ----------------
// Block 128x128, BK=32, 128 threads = 4 warps, warp tile 64x64.
__device__ __forceinline__ unsigned f2tf(float x) {
    unsigned u;
    asm("cvt.rna.tf32.f32 %0, %1;" : "=r"(u) : "f"(x));
    return u;
}

__global__ void __launch_bounds__(128)
k_gemm_tf32(const float* __restrict__ A, const float* __restrict__ B,
            const float* __restrict__ bias, float* __restrict__ C,
            int M, int N, int K, int relu) {
    __shared__ float As[128][36];    // [m][k], pad 4
    __shared__ float Bs[32][136];    // [k][n], pad 8

    const int tid = threadIdx.x;
    const int wid = tid >> 5, lane = tid & 31;
    const int g = lane >> 2, t = lane & 3;
    const int wr = (wid >> 1) * 64;
    const int wc = (wid & 1) * 64;
    const int rowBase = blockIdx.y * 128;
    const int colBase = blockIdx.x * 128;

    float acc[4][8][4];
#pragma unroll
    for (int i = 0; i < 4; i++)
#pragma unroll
        for (int j = 0; j < 8; j++)
#pragma unroll
            for (int k = 0; k < 4; k++) acc[i][j][k] = 0.f;

    for (int k0 = 0; k0 < K; k0 += 32) {
#pragma unroll
        for (int i = 0; i < 8; i++) {
            int c = i * 128 + tid;
            int m = c >> 3, kc = (c & 7) * 4;
            int gr = rowBase + m;
            float4 v = (gr < M) ? *(const float4*)(A + (size_t)gr * K + k0 + kc)
                                : make_float4(0.f, 0.f, 0.f, 0.f);
            As[m][kc + 0] = __uint_as_float(f2tf(v.x));
            As[m][kc + 1] = __uint_as_float(f2tf(v.y));
            As[m][kc + 2] = __uint_as_float(f2tf(v.z));
            As[m][kc + 3] = __uint_as_float(f2tf(v.w));
        }
#pragma unroll
        for (int i = 0; i < 8; i++) {
            int c = i * 128 + tid;
            int k = c >> 5, nc = (c & 31) * 4;
            float4 v = *(const float4*)(B + (size_t)(k0 + k) * N + colBase + nc);
            float4 w;
            w.x = __uint_as_float(f2tf(v.x));
            w.y = __uint_as_float(f2tf(v.y));
            w.z = __uint_as_float(f2tf(v.z));
            w.w = __uint_as_float(f2tf(v.w));
            *(float4*)&Bs[k][nc] = w;
        }
        __syncthreads();

#pragma unroll
        for (int kk = 0; kk < 4; kk++) {
            const int kb = kk * 8;
            uint32_t a[4][4], b[8][2];
#pragma unroll
            for (int mi = 0; mi < 4; mi++) {
                int r = wr + mi * 16 + g;
                a[mi][0] = __float_as_uint(As[r][kb + t]);
                a[mi][1] = __float_as_uint(As[r + 8][kb + t]);
                a[mi][2] = __float_as_uint(As[r][kb + t + 4]);
                a[mi][3] = __float_as_uint(As[r + 8][kb + t + 4]);
            }
#pragma unroll
            for (int ni = 0; ni < 8; ni++) {
                int cn = wc + ni * 8 + g;
                b[ni][0] = __float_as_uint(Bs[kb + t][cn]);
                b[ni][1] = __float_as_uint(Bs[kb + t + 4][cn]);
            }
#pragma unroll
            for (int mi = 0; mi < 4; mi++)
#pragma unroll
                for (int ni = 0; ni < 8; ni++) {
                    asm volatile(
                        "mma.sync.aligned.m16n8k8.row.col.f32.tf32.tf32.f32 "
                        "{%0,%1,%2,%3}, {%4,%5,%6,%7}, {%8,%9}, {%0,%1,%2,%3};"
                        : "+f"(acc[mi][ni][0]), "+f"(acc[mi][ni][1]),
                          "+f"(acc[mi][ni][2]), "+f"(acc[mi][ni][3])
                        : "r"(a[mi][0]), "r"(a[mi][1]), "r"(a[mi][2]), "r"(a[mi][3]),
                          "r"(b[ni][0]), "r"(b[ni][1]));
                }
        }
        __syncthreads();
    }

#pragma unroll
    for (int mi = 0; mi < 4; mi++) {
        int r0 = rowBase + wr + mi * 16 + g;
#pragma unroll
        for (int half = 0; half < 2; half++) {
            int r = r0 + half * 8;
            if (r >= M) continue;
#pragma unroll
            for (int ni = 0; ni < 8; ni++) {
                int col = colBase + wc + ni * 8 + 2 * t;
                float v0 = acc[mi][ni][half * 2 + 0] + bias[col];
                float v1 = acc[mi][ni][half * 2 + 1] + bias[col + 1];
                if (relu) {
                    v0 = fmaxf(v0, 0.f);
                    v1 = fmaxf(v1, 0.f);
                }
                *(float2*)(C + (size_t)r * N + col) = make_float2(v0, v1);
            }
        }
    }
}

// ---------------- global max pool (batch is sorted) ----------------
__global__ void k_gstart(const int* __restrict__ batch, int* __restrict__ gstart) {
    int i = blockIdx.x * blockDim.x + threadIdx.x;
    if (i >= NN) return;
    if (i == 0) {
        gstart[0] = 0;
        gstart[NG] = NN;
    } else if (batch[i] != batch[i - 1]) {
        gstart[batch[i]] = i;
    }
}

__global__ void k_pool_max(const float* __restrict__ h, const int* __restrict__ gstart,
                           float* __restrict__ g) {
    int gr = blockIdx.x;
    int f = threadIdx.x;
    int s = gstart[gr], e = gstart[gr + 1];
    float m = -3.4e38f;
    for (int i = s; i < e; i++) m = fmaxf(m, h[(size_t)i * 512 + f]);
    g[gr * 512 + f] = m;
}

// ---------------- launch ----------------
extern "C" void kernel_launch(void* const* d_in, const int* in_sizes, int n_in,
                              void* d_out, int out_size) {
    const float* x   = (const float*)d_in[0];
    const float* ew  = (const float*)d_in[1];
    const float* W1  = (const float*)d_in[2];
    const float* b1  = (const float*)d_in[3];
    const float* W2  = (const float*)d_in[4];
    const float* b2  = (const float*)d_in[5];
    const float* W3  = (const float*)d_in[6];
    const float* b3  = (const float*)d_in[7];
    const float* Wf1 = (const float*)d_in[8];
    const float* bf1 = (const float*)d_in[9];
    const float* Wf2 = (const float*)d_in[10];
    const float* bf2 = (const float*)d_in[11];
    const int* ei    = (const int*)d_in[12];    // int32 (JAX x64 disabled)
    const int* batch = (const int*)d_in[13];    // int32
    float* out = (float*)d_out;

    void *p;
    cudaGetSymbolAddress(&p, g_deg);    float* deg   = (float*)p;
    cudaGetSymbolAddress(&p, g_dinv);   float* dinv  = (float*)p;
    cudaGetSymbolAddress(&p, g_cnt);    int*   cnt   = (int*)p;
    cudaGetSymbolAddress(&p, g_rowptr); int*   rowp  = (int*)p;
    cudaGetSymbolAddress(&p, g_part);   int*   part  = (int*)p;
    cudaGetSymbolAddress(&p, g_esrc);   int*   esrc  = (int*)p;
    cudaGetSymbolAddress(&p, g_ecoef);  float* ecoef = (float*)p;
    cudaGetSymbolAddress(&p, g_agg);    float* agg   = (float*)p;
    cudaGetSymbolAddress(&p, g_h1);     float* h1    = (float*)p;
    cudaGetSymbolAddress(&p, g_h2);     float* h2    = (float*)p;
    cudaGetSymbolAddress(&p, g_h3);     float* h3    = (float*)p;
    cudaGetSymbolAddress(&p, g_pool);   float* pool  = (float*)p;
    cudaGetSymbolAddress(&p, g_fc1);    float* fc1   = (float*)p;
    cudaGetSymbolAddress(&p, g_gstart); int*   gst   = (int*)p;

    const int T = 256;
    // ---- normalization prep + CSR build ----
    k_deg_init<<<(NN + T - 1) / T, T>>>(deg, cnt);
    k_deg_edges<<<(NE + T - 1) / T, T>>>(ei, ew, deg, cnt);
    k_dinv<<<(NN + T - 1) / T, T>>>(deg, dinv);
    k_scan_part<<<SCAN_B, 256>>>(cnt, part);
    k_scan_top<<<1, SCAN_B>>>(part, rowp);
    k_scan_fin<<<SCAN_B, 256>>>(cnt, part, rowp);
    k_edge_scatter<<<(NE + T - 1) / T, T>>>(ei, ew, dinv, rowp, cnt, esrc, ecoef);

    const int MB = (NN + 127) / 128;       // 391 row tiles
    const int GW = (NN * 32 + T - 1) / T;  // gather: warp per node

    // ---- layer 1 ----
    k_gather<128><<<GW, T>>>(rowp, esrc, ecoef, dinv, x, agg);
    k_gemm_tf32<<<dim3(1, MB), 128>>>(agg, W1, b1, h1, NN, 128, 128, 1);

    // ---- layer 2 ----
    k_gather<128><<<GW, T>>>(rowp, esrc, ecoef, dinv, h1, agg);
    k_gemm_tf32<<<dim3(2, MB), 128>>>(agg, W2, b2, h2, NN, 256, 128, 1);

    // ---- layer 3 ----
    k_gather<256><<<GW, T>>>(rowp, esrc, ecoef, dinv, h2, agg);
    k_gemm_tf32<<<dim3(4, MB), 128>>>(agg, W3, b3, h3, NN, 512, 256, 1);

    // ---- global max pool ----
    k_gstart<<<(NN + T - 1) / T, T>>>(batch, gst);
    k_pool_max<<<NG, 512>>>(h3, gst, pool);

    // ---- FC head ----
    k_gemm_tf32<<<dim3(8, 4), 128>>>(pool, Wf1, bf1, fc1, NG, 1024, 512, 1);
    k_gemm_tf32<<<dim3(1, 4), 128>>>(fc1, Wf2, bf2, out, NG, 128, 1024, 0);
}

// round 15
// speedup vs baseline: 2.4378x; 1.0821x over previous
#include <cuda_runtime.h>
#include <cstdint>

#define NN 50000
#define NE 800000
#define NG 512

#define SCAN_B 256
#define SCAN_CH 196   // 256*196 = 50176 >= NN

// ---------------- scratch (float4 => 16B aligned) ----------------
__device__ float  g_deg[NN];
__device__ float  g_dinv[NN];
__device__ int    g_cnt[NN];          // edge counts, reused as scatter cursor
__device__ int    g_rowptr[NN + 1];
__device__ int    g_part[SCAN_B];
__device__ int    g_esrc[NE];         // CSR-sorted src
__device__ float  g_ecoef[NE];        // CSR-sorted coef
__device__ float4 g_agg [(size_t)NN * 256 / 4];
__device__ float4 g_h1  [(size_t)NN * 128 / 4];
__device__ float4 g_h2  [(size_t)NN * 256 / 4];
__device__ float4 g_h3  [(size_t)NN * 512 / 4];
__device__ float4 g_pool[NG * 512 / 4];
__device__ float4 g_fc1 [NG * 1024 / 4];
__device__ int    g_gstart[NG + 1];

// ---------------- degree / count prep ----------------
__global__ void k_deg_init(float* deg, int* cnt) {
    int i = blockIdx.x * blockDim.x + threadIdx.x;
    if (i < NN) {
        deg[i] = 1.0f;  // self-loop weight
        cnt[i] = 0;
    }
}

// fused: weighted degree + edge count per destination
__global__ void k_deg_edges(const int* __restrict__ ei,
                            const float* __restrict__ ew,
                            float* deg, int* cnt) {
    int e = blockIdx.x * blockDim.x + threadIdx.x;
    if (e >= NE) return;
    int d = ei[NE + e];
    atomicAdd(&deg[d], ew[e]);
    atomicAdd(&cnt[d], 1);
}

// ---------------- 3-phase parallel exclusive scan ----------------
// phase 1: per-block chunk sums
__global__ void k_scan_part(const int* __restrict__ cnt, int* __restrict__ part) {
    __shared__ int s[256];
    int b = blockIdx.x, t = threadIdx.x;
    int idx = b * SCAN_CH + t;
    s[t] = (t < SCAN_CH && idx < NN) ? cnt[idx] : 0;
    __syncthreads();
    for (int off = 128; off > 0; off >>= 1) {
        if (t < off) s[t] += s[t + off];
        __syncthreads();
    }
    if (t == 0) part[b] = s[0];
}

// phase 2: exclusive scan of the 256 block sums (single block)
__global__ void k_scan_top(int* __restrict__ part, int* __restrict__ rowptr) {
    __shared__ int s[SCAN_B];
    int t = threadIdx.x;
    int v = part[t];
    s[t] = v;
    __syncthreads();
    for (int off = 1; off < SCAN_B; off <<= 1) {
        int u = (t >= off) ? s[t - off] : 0;
        __syncthreads();
        s[t] += u;
        __syncthreads();
    }
    part[t] = s[t] - v;  // exclusive
    if (t == SCAN_B - 1) rowptr[NN] = s[t];
}

// phase 3: local scan + offset; zero cnt; fused dinv = rsqrt(deg)
__global__ void k_scan_fin(int* __restrict__ cnt, const int* __restrict__ part,
                           int* __restrict__ rowptr,
                           const float* __restrict__ deg, float* __restrict__ dinv) {
    __shared__ int s[256];
    int b = blockIdx.x, t = threadIdx.x;
    int idx = b * SCAN_CH + t;
    int v = (t < SCAN_CH && idx < NN) ? cnt[idx] : 0;
    s[t] = v;
    __syncthreads();
    for (int off = 1; off < 256; off <<= 1) {
        int u = (t >= off) ? s[t - off] : 0;
        __syncthreads();
        s[t] += u;
        __syncthreads();
    }
    if (t < SCAN_CH && idx < NN) {
        rowptr[idx] = part[b] + s[t] - v;  // exclusive
        cnt[idx] = 0;                       // reset cursor
        float d = deg[idx];
        dinv[idx] = (d > 0.f) ? rsqrtf(d) : 0.f;
    }
}

// fused: compute coef + scatter into CSR slots (no temp arrays)
__global__ void k_edge_scatter(const int* __restrict__ ei,
                               const float* __restrict__ ew,
                               const float* __restrict__ dinv,
                               const int* __restrict__ rowptr, int* __restrict__ cur,
                               int* __restrict__ esrc, float* __restrict__ ecoef) {
    int e = blockIdx.x * blockDim.x + threadIdx.x;
    if (e >= NE) return;
    int s = ei[e];
    int d = ei[NE + e];
    int pos = rowptr[d] + atomicAdd(&cur[d], 1);
    esrc[pos] = s;
    ecoef[pos] = dinv[s] * ew[e] * dinv[d];
}

// ---------------- CSR gather aggregation (no atomics) ----------------
template <int F>
__global__ void k_gather(const int* __restrict__ rowptr, const int* __restrict__ esrc,
                         const float* __restrict__ ecoef, const float* __restrict__ dinv,
                         const float* __restrict__ h, float* __restrict__ out) {
    int w = (blockIdx.x * blockDim.x + threadIdx.x) >> 5;
    int lane = threadIdx.x & 31;
    if (w >= NN) return;
    constexpr int C = F / 128;
    float4 acc[C];
    {
        float s = dinv[w];
        s *= s;
#pragma unroll
        for (int j = 0; j < C; j++) {
            float4 v = *(const float4*)(h + (size_t)w * F + j * 128 + lane * 4);
            acc[j] = make_float4(v.x * s, v.y * s, v.z * s, v.w * s);
        }
    }
    int e = rowptr[w], eEnd = rowptr[w + 1];
    for (; e + 3 < eEnd; e += 4) {
        int s0 = esrc[e], s1 = esrc[e + 1], s2 = esrc[e + 2], s3 = esrc[e + 3];
        float c0 = ecoef[e], c1 = ecoef[e + 1], c2 = ecoef[e + 2], c3 = ecoef[e + 3];
#pragma unroll
        for (int j = 0; j < C; j++) {
            const size_t off = j * 128 + lane * 4;
            float4 v0 = *(const float4*)(h + (size_t)s0 * F + off);
            float4 v1 = *(const float4*)(h + (size_t)s1 * F + off);
            float4 v2 = *(const float4*)(h + (size_t)s2 * F + off);
            float4 v3 = *(const float4*)(h + (size_t)s3 * F + off);
            acc[j].x += v0.x * c0 + v1.x * c1 + v2.x * c2 + v3.x * c3;
            acc[j].y += v0.y * c0 + v1.y * c1 + v2.y * c2 + v3.y * c3;
            acc[j].z += v0.z * c0 + v1.z * c1 + v2.z * c2 + v3.z * c3;
            acc[j].w += v0.w * c0 + v1.w * c1 + v2.w * c2 + v3.w * c3;
        }
    }
    for (; e < eEnd; e++) {
        int s0 = esrc[e];
        float c0 = ecoef[e];
#pragma unroll
        for (int j = 0; j < C; j++) {
            float4 v0 = *(const float4*)(h + (size_t)s0 * F + j * 128 + lane * 4);
            acc[j].x += v0.x * c0;
            acc[j].y += v0.y * c0;
            acc[j].z += v0.z * c0;
            acc[j].w += v0.w * c0;
        }
    }
#pragma unroll
    for (int j = 0; j < C; j++)
        *(float4*)(out + (size_t)w * F + j * 128 + lane * 4) = acc[j];
}

// ---------------- TF32 mma GEMM + bias + relu (templated tile) ----------------
// Block BMxBN, BK=32, 128 threads = 4 warps (2x2), warp tile (BM/2)x(BN/2).
__device__ __forceinline__ unsigned f2tf(float x) {
    unsigned u;
    asm("cvt.rna.tf32.f32 %0, %1;" : "=r"(u) : "f"(x));
    return u;
}

template <int BM, int BN>
__global__ void __launch_bounds__(128)
k_gemm_tf32(const float* __restrict__ A, const float* __restrict__ B,
            const float* __restrict__ bias, float* __restrict__ C,
            int M, int N, int K, int relu) {
    constexpr int MI = BM / 32;   // mi steps per warp
    constexpr int NI = BN / 16;   // ni steps per warp
    __shared__ float As[BM][36];       // [m][k], pad 4
    __shared__ float Bs[32][BN + 8];   // [k][n], pad 8

    const int tid = threadIdx.x;
    const int wid = tid >> 5, lane = tid & 31;
    const int g = lane >> 2, t = lane & 3;
    const int wr = (wid >> 1) * (BM / 2);
    const int wc = (wid & 1) * (BN / 2);
    const int rowBase = blockIdx.y * BM;
    const int colBase = blockIdx.x * BN;

    float acc[MI][NI][4];
#pragma unroll
    for (int i = 0; i < MI; i++)
#pragma unroll
        for (int j = 0; j < NI; j++)
#pragma unroll
            for (int k = 0; k < 4; k++) acc[i][j][k] = 0.f;

    for (int k0 = 0; k0 < K; k0 += 32) {
        // A tile: BM*8 float4 chunks / 128 threads
#pragma unroll
        for (int i = 0; i < BM / 16; i++) {
            int c = i * 128 + tid;
            int m = c >> 3, kc = (c & 7) * 4;
            int gr = rowBase + m;
            float4 v = (gr < M) ? *(const float4*)(A + (size_t)gr * K + k0 + kc)
                                : make_float4(0.f, 0.f, 0.f, 0.f);
            As[m][kc + 0] = __uint_as_float(f2tf(v.x));
            As[m][kc + 1] = __uint_as_float(f2tf(v.y));
            As[m][kc + 2] = __uint_as_float(f2tf(v.z));
            As[m][kc + 3] = __uint_as_float(f2tf(v.w));
        }
        // B tile: 32 rows x BN/4 float4 chunks
#pragma unroll
        for (int i = 0; i < BN / 16; i++) {
            int c = i * 128 + tid;
            int k = c / (BN / 4), nc = (c % (BN / 4)) * 4;
            float4 v = *(const float4*)(B + (size_t)(k0 + k) * N + colBase + nc);
            float4 w;
            w.x = __uint_as_float(f2tf(v.x));
            w.y = __uint_as_float(f2tf(v.y));
            w.z = __uint_as_float(f2tf(v.z));
            w.w = __uint_as_float(f2tf(v.w));
            *(float4*)&Bs[k][nc] = w;
        }
        __syncthreads();

#pragma unroll
        for (int kk = 0; kk < 4; kk++) {
            const int kb = kk * 8;
            uint32_t a[MI][4], b[NI][2];
#pragma unroll
            for (int mi = 0; mi < MI; mi++) {
                int r = wr + mi * 16 + g;
                a[mi][0] = __float_as_uint(As[r][kb + t]);
                a[mi][1] = __float_as_uint(As[r + 8][kb + t]);
                a[mi][2] = __float_as_uint(As[r][kb + t + 4]);
                a[mi][3] = __float_as_uint(As[r + 8][kb + t + 4]);
            }
#pragma unroll
            for (int ni = 0; ni < NI; ni++) {
                int cn = wc + ni * 8 + g;
                b[ni][0] = __float_as_uint(Bs[kb + t][cn]);
                b[ni][1] = __float_as_uint(Bs[kb + t + 4][cn]);
            }
#pragma unroll
            for (int mi = 0; mi < MI; mi++)
#pragma unroll
                for (int ni = 0; ni < NI; ni++) {
                    asm volatile(
                        "mma.sync.aligned.m16n8k8.row.col.f32.tf32.tf32.f32 "
                        "{%0,%1,%2,%3}, {%4,%5,%6,%7}, {%8,%9}, {%0,%1,%2,%3};"
                        : "+f"(acc[mi][ni][0]), "+f"(acc[mi][ni][1]),
                          "+f"(acc[mi][ni][2]), "+f"(acc[mi][ni][3])
                        : "r"(a[mi][0]), "r"(a[mi][1]), "r"(a[mi][2]), "r"(a[mi][3]),
                          "r"(b[ni][0]), "r"(b[ni][1]));
                }
        }
        __syncthreads();
    }

#pragma unroll
    for (int mi = 0; mi < MI; mi++) {
        int r0 = rowBase + wr + mi * 16 + g;
#pragma unroll
        for (int half = 0; half < 2; half++) {
            int r = r0 + half * 8;
            if (r >= M) continue;
#pragma unroll
            for (int ni = 0; ni < NI; ni++) {
                int col = colBase + wc + ni * 8 + 2 * t;
                float v0 = acc[mi][ni][half * 2 + 0] + bias[col];
                float v1 = acc[mi][ni][half * 2 + 1] + bias[col + 1];
                if (relu) {
                    v0 = fmaxf(v0, 0.f);
                    v1 = fmaxf(v1, 0.f);
                }
                *(float2*)(C + (size_t)r * N + col) = make_float2(v0, v1);
            }
        }
    }
}

// ---------------- global max pool (batch is sorted) ----------------
__global__ void k_gstart(const int* __restrict__ batch, int* __restrict__ gstart) {
    int i = blockIdx.x * blockDim.x + threadIdx.x;
    if (i >= NN) return;
    if (i == 0) {
        gstart[0] = 0;
        gstart[NG] = NN;
    } else if (batch[i] != batch[i - 1]) {
        gstart[batch[i]] = i;
    }
}

__global__ void k_pool_max(const float* __restrict__ h, const int* __restrict__ gstart,
                           float* __restrict__ g) {
    int gr = blockIdx.x;
    int f = threadIdx.x;
    int s = gstart[gr], e = gstart[gr + 1];
    float m = -3.4e38f;
    for (int i = s; i < e; i++) m = fmaxf(m, h[(size_t)i * 512 + f]);
    g[gr * 512 + f] = m;
}

// ---------------- launch ----------------
extern "C" void kernel_launch(void* const* d_in, const int* in_sizes, int n_in,
                              void* d_out, int out_size) {
    const float* x   = (const float*)d_in[0];
    const float* ew  = (const float*)d_in[1];
    const float* W1  = (const float*)d_in[2];
    const float* b1  = (const float*)d_in[3];
    const float* W2  = (const float*)d_in[4];
    const float* b2  = (const float*)d_in[5];
    const float* W3  = (const float*)d_in[6];
    const float* b3  = (const float*)d_in[7];
    const float* Wf1 = (const float*)d_in[8];
    const float* bf1 = (const float*)d_in[9];
    const float* Wf2 = (const float*)d_in[10];
    const float* bf2 = (const float*)d_in[11];
    const int* ei    = (const int*)d_in[12];    // int32 (JAX x64 disabled)
    const int* batch = (const int*)d_in[13];    // int32
    float* out = (float*)d_out;

    void *p;
    cudaGetSymbolAddress(&p, g_deg);    float* deg   = (float*)p;
    cudaGetSymbolAddress(&p, g_dinv);   float* dinv  = (float*)p;
    cudaGetSymbolAddress(&p, g_cnt);    int*   cnt   = (int*)p;
    cudaGetSymbolAddress(&p, g_rowptr); int*   rowp  = (int*)p;
    cudaGetSymbolAddress(&p, g_part);   int*   part  = (int*)p;
    cudaGetSymbolAddress(&p, g_esrc);   int*   esrc  = (int*)p;
    cudaGetSymbolAddress(&p, g_ecoef);  float* ecoef = (float*)p;
    cudaGetSymbolAddress(&p, g_agg);    float* agg   = (float*)p;
    cudaGetSymbolAddress(&p, g_h1);     float* h1    = (float*)p;
    cudaGetSymbolAddress(&p, g_h2);     float* h2    = (float*)p;
    cudaGetSymbolAddress(&p, g_h3);     float* h3    = (float*)p;
    cudaGetSymbolAddress(&p, g_pool);   float* pool  = (float*)p;
    cudaGetSymbolAddress(&p, g_fc1);    float* fc1   = (float*)p;
    cudaGetSymbolAddress(&p, g_gstart); int*   gst   = (int*)p;

    const int T = 256;
    // ---- normalization prep + CSR build ----
    k_deg_init<<<(NN + T - 1) / T, T>>>(deg, cnt);
    k_deg_edges<<<(NE + T - 1) / T, T>>>(ei, ew, deg, cnt);
    k_scan_part<<<SCAN_B, 256>>>(cnt, part);
    k_scan_top<<<1, SCAN_B>>>(part, rowp);
    k_scan_fin<<<SCAN_B, 256>>>(cnt, part, rowp, deg, dinv);
    k_edge_scatter<<<(NE + T - 1) / T, T>>>(ei, ew, dinv, rowp, cnt, esrc, ecoef);

    const int MB = (NN + 127) / 128;       // 391 row tiles
    const int GW = (NN * 32 + T - 1) / T;  // gather: warp per node

    // ---- layer 1 ----
    k_gather<128><<<GW, T>>>(rowp, esrc, ecoef, dinv, x, agg);
    k_gemm_tf32<128, 128><<<dim3(1, MB), 128>>>(agg, W1, b1, h1, NN, 128, 128, 1);

    // ---- layer 2 ----
    k_gather<128><<<GW, T>>>(rowp, esrc, ecoef, dinv, h1, agg);
    k_gemm_tf32<128, 128><<<dim3(2, MB), 128>>>(agg, W2, b2, h2, NN, 256, 128, 1);

    // ---- layer 3 ----
    k_gather<256><<<GW, T>>>(rowp, esrc, ecoef, dinv, h2, agg);
    k_gemm_tf32<128, 128><<<dim3(4, MB), 128>>>(agg, W3, b3, h3, NN, 512, 256, 1);

    // ---- global max pool ----
    k_gstart<<<(NN + T - 1) / T, T>>>(batch, gst);
    k_pool_max<<<NG, 512>>>(h3, gst, pool);

    // ---- FC head (64x64 tiles: fc1 = 128 blocks, fc2 = 16 blocks) ----
    k_gemm_tf32<64, 64><<<dim3(1024 / 64, NG / 64), 128>>>(pool, Wf1, bf1, fc1, NG, 1024, 512, 1);
    k_gemm_tf32<64, 64><<<dim3(128 / 64, NG / 64), 128>>>(fc1, Wf2, bf2, out, NG, 128, 1024, 0);
}

// round 16
// speedup vs baseline: 2.7005x; 1.1077x over previous
#include <cuda_runtime.h>
#include <cstdint>

#define NN 50000
#define NE 800000
#define NG 512

#define SCAN_B 256
#define SCAN_CH 196   // 256*196 = 50176 >= NN

// ---------------- scratch (float4 => 16B aligned) ----------------
__device__ float  g_deg[NN];
__device__ float  g_dinv[NN];
__device__ int    g_cnt[NN];          // edge counts, reused as scatter cursor
__device__ int    g_rowptr[NN + 1];
__device__ int    g_part[SCAN_B];
__device__ int    g_esrc[NE];         // CSR-sorted src
__device__ float  g_ecoef[NE];        // CSR-sorted coef
__device__ float4 g_agg [(size_t)NN * 256 / 4];
__device__ float4 g_h1  [(size_t)NN * 128 / 4];
__device__ float4 g_h2  [(size_t)NN * 256 / 4];
__device__ float4 g_h3  [(size_t)NN * 512 / 4];
__device__ float4 g_pool[NG * 512 / 4];
__device__ float4 g_fc1 [NG * 1024 / 4];
__device__ int    g_gstart[NG + 1];

// ---------------- degree / count prep ----------------
__global__ void k_deg_init(float* deg, int* cnt) {
    int i = blockIdx.x * blockDim.x + threadIdx.x;
    if (i < NN) {
        deg[i] = 1.0f;  // self-loop weight
        cnt[i] = 0;
    }
}

__global__ void k_deg_edges(const int* __restrict__ ei,
                            const float* __restrict__ ew,
                            float* deg, int* cnt) {
    int e = blockIdx.x * blockDim.x + threadIdx.x;
    if (e >= NE) return;
    int d = ei[NE + e];
    atomicAdd(&deg[d], ew[e]);
    atomicAdd(&cnt[d], 1);
}

// ---------------- 3-phase parallel exclusive scan ----------------
__global__ void k_scan_part(const int* __restrict__ cnt, int* __restrict__ part) {
    __shared__ int s[256];
    int b = blockIdx.x, t = threadIdx.x;
    int idx = b * SCAN_CH + t;
    s[t] = (t < SCAN_CH && idx < NN) ? cnt[idx] : 0;
    __syncthreads();
    for (int off = 128; off > 0; off >>= 1) {
        if (t < off) s[t] += s[t + off];
        __syncthreads();
    }
    if (t == 0) part[b] = s[0];
}

__global__ void k_scan_top(int* __restrict__ part, int* __restrict__ rowptr) {
    __shared__ int s[SCAN_B];
    int t = threadIdx.x;
    int v = part[t];
    s[t] = v;
    __syncthreads();
    for (int off = 1; off < SCAN_B; off <<= 1) {
        int u = (t >= off) ? s[t - off] : 0;
        __syncthreads();
        s[t] += u;
        __syncthreads();
    }
    part[t] = s[t] - v;  // exclusive
    if (t == SCAN_B - 1) rowptr[NN] = s[t];
}

// phase 3 + fused dinv = rsqrt(deg)
__global__ void k_scan_fin(int* __restrict__ cnt, const int* __restrict__ part,
                           int* __restrict__ rowptr,
                           const float* __restrict__ deg, float* __restrict__ dinv) {
    __shared__ int s[256];
    int b = blockIdx.x, t = threadIdx.x;
    int idx = b * SCAN_CH + t;
    int v = (t < SCAN_CH && idx < NN) ? cnt[idx] : 0;
    s[t] = v;
    __syncthreads();
    for (int off = 1; off < 256; off <<= 1) {
        int u = (t >= off) ? s[t - off] : 0;
        __syncthreads();
        s[t] += u;
        __syncthreads();
    }
    if (t < SCAN_CH && idx < NN) {
        rowptr[idx] = part[b] + s[t] - v;  // exclusive
        cnt[idx] = 0;                       // reset cursor
        float d = deg[idx];
        dinv[idx] = (d > 0.f) ? rsqrtf(d) : 0.f;
    }
}

__global__ void k_edge_scatter(const int* __restrict__ ei,
                               const float* __restrict__ ew,
                               const float* __restrict__ dinv,
                               const int* __restrict__ rowptr, int* __restrict__ cur,
                               int* __restrict__ esrc, float* __restrict__ ecoef) {
    int e = blockIdx.x * blockDim.x + threadIdx.x;
    if (e >= NE) return;
    int s = ei[e];
    int d = ei[NE + e];
    int pos = rowptr[d] + atomicAdd(&cur[d], 1);
    esrc[pos] = s;
    ecoef[pos] = dinv[s] * ew[e] * dinv[d];
}

// ---------------- CSR gather aggregation (no atomics) ----------------
template <int F>
__global__ void k_gather(const int* __restrict__ rowptr, const int* __restrict__ esrc,
                         const float* __restrict__ ecoef, const float* __restrict__ dinv,
                         const float* __restrict__ h, float* __restrict__ out) {
    int w = (blockIdx.x * blockDim.x + threadIdx.x) >> 5;
    int lane = threadIdx.x & 31;
    if (w >= NN) return;
    constexpr int C = F / 128;
    float4 acc[C];
    {
        float s = dinv[w];
        s *= s;
#pragma unroll
        for (int j = 0; j < C; j++) {
            float4 v = *(const float4*)(h + (size_t)w * F + j * 128 + lane * 4);
            acc[j] = make_float4(v.x * s, v.y * s, v.z * s, v.w * s);
        }
    }
    int e = rowptr[w], eEnd = rowptr[w + 1];
    for (; e + 3 < eEnd; e += 4) {
        int s0 = esrc[e], s1 = esrc[e + 1], s2 = esrc[e + 2], s3 = esrc[e + 3];
        float c0 = ecoef[e], c1 = ecoef[e + 1], c2 = ecoef[e + 2], c3 = ecoef[e + 3];
#pragma unroll
        for (int j = 0; j < C; j++) {
            const size_t off = j * 128 + lane * 4;
            float4 v0 = *(const float4*)(h + (size_t)s0 * F + off);
            float4 v1 = *(const float4*)(h + (size_t)s1 * F + off);
            float4 v2 = *(const float4*)(h + (size_t)s2 * F + off);
            float4 v3 = *(const float4*)(h + (size_t)s3 * F + off);
            acc[j].x += v0.x * c0 + v1.x * c1 + v2.x * c2 + v3.x * c3;
            acc[j].y += v0.y * c0 + v1.y * c1 + v2.y * c2 + v3.y * c3;
            acc[j].z += v0.z * c0 + v1.z * c1 + v2.z * c2 + v3.z * c3;
            acc[j].w += v0.w * c0 + v1.w * c1 + v2.w * c2 + v3.w * c3;
        }
    }
    for (; e < eEnd; e++) {
        int s0 = esrc[e];
        float c0 = ecoef[e];
#pragma unroll
        for (int j = 0; j < C; j++) {
            float4 v0 = *(const float4*)(h + (size_t)s0 * F + j * 128 + lane * 4);
            acc[j].x += v0.x * c0;
            acc[j].y += v0.y * c0;
            acc[j].z += v0.z * c0;
            acc[j].w += v0.w * c0;
        }
    }
#pragma unroll
    for (int j = 0; j < C; j++)
        *(float4*)(out + (size_t)w * F + j * 128 + lane * 4) = acc[j];
}

// ---------------- TF32 mma GEMM + bias + relu (cp.async double-buffered) ----------------
// Block BMxBN, BK=32, 128 threads = 4 warps (2x2), warp tile (BM/2)x(BN/2).
// Raw fp32 tiles land in smem via cp.async; tf32 convert (RNA) on fragments.
__device__ __forceinline__ unsigned f2tf(float x) {
    unsigned u;
    asm("cvt.rna.tf32.f32 %0, %1;" : "=r"(u) : "f"(x));
    return u;
}
__device__ __forceinline__ uint32_t smem_u32(const void* p) {
    uint32_t a;
    asm("{ .reg .u64 t; cvta.to.shared.u64 t, %1; cvt.u32.u64 %0, t; }" : "=r"(a) : "l"(p));
    return a;
}
__device__ __forceinline__ void cp16(uint32_t dst, const void* src, int srcBytes) {
    asm volatile("cp.async.cg.shared.global [%0], [%1], 16, %2;"
                 :: "r"(dst), "l"(src), "r"(srcBytes) : "memory");
}

#define AS_STRIDE 36

template <int BM, int BN>
__global__ void __launch_bounds__(128)
k_gemm_tf32(const float* __restrict__ A, const float* __restrict__ B,
            const float* __restrict__ bias, float* __restrict__ C,
            int M, int N, int K, int relu) {
    constexpr int MI = BM / 32;
    constexpr int NI = BN / 16;
    constexpr int BS_STRIDE = BN + 8;
    constexpr int A_BUF = BM * AS_STRIDE;     // floats per A buffer
    constexpr int B_BUF = 32 * BS_STRIDE;     // floats per B buffer

    extern __shared__ float smem[];
    float* As = smem;                  // [2][BM][AS_STRIDE]
    float* Bs = smem + 2 * A_BUF;      // [2][32][BS_STRIDE]
    const uint32_t asBase = smem_u32(As);
    const uint32_t bsBase = smem_u32(Bs);

    const int tid = threadIdx.x;
    const int wid = tid >> 5, lane = tid & 31;
    const int g = lane >> 2, t = lane & 3;
    const int wr = (wid >> 1) * (BM / 2);
    const int wc = (wid & 1) * (BN / 2);
    const int rowBase = blockIdx.y * BM;
    const int colBase = blockIdx.x * BN;

    // async-load one k-tile into buffer `buf`
    auto loadTiles = [&](int k0, int buf) {
#pragma unroll
        for (int i = 0; i < BM / 16; i++) {
            int c = i * 128 + tid;
            int m = c >> 3, kc = (c & 7) * 4;
            int gr = rowBase + m;
            uint32_t dst = asBase + (uint32_t)(buf * A_BUF + m * AS_STRIDE + kc) * 4u;
            const float* src = A + (size_t)gr * K + k0 + kc;   // only deref'd by HW if srcBytes>0
            cp16(dst, src, (gr < M) ? 16 : 0);
        }
#pragma unroll
        for (int i = 0; i < BN / 16; i++) {
            int c = i * 128 + tid;
            int k = c / (BN / 4), nc = (c % (BN / 4)) * 4;
            uint32_t dst = bsBase + (uint32_t)(buf * B_BUF + k * BS_STRIDE + nc) * 4u;
            cp16(dst, B + (size_t)(k0 + k) * N + colBase + nc, 16);
        }
        asm volatile("cp.async.commit_group;" ::: "memory");
    };

    float acc[MI][NI][4];
#pragma unroll
    for (int i = 0; i < MI; i++)
#pragma unroll
        for (int j = 0; j < NI; j++)
#pragma unroll
            for (int k = 0; k < 4; k++) acc[i][j][k] = 0.f;

    const int T = K >> 5;
    loadTiles(0, 0);                       // prologue

    for (int tt = 0; tt < T; tt++) {
        const int buf = tt & 1;
        const bool more = (tt + 1) < T;
        if (more) loadTiles((tt + 1) << 5, buf ^ 1);
        if (more) asm volatile("cp.async.wait_group 1;" ::: "memory");
        else      asm volatile("cp.async.wait_group 0;" ::: "memory");
        __syncthreads();

        const float* Ab = As + buf * A_BUF;
        const float* Bb = Bs + buf * B_BUF;
#pragma unroll
        for (int kk = 0; kk < 4; kk++) {
            const int kb = kk * 8;
            uint32_t a[MI][4], b[NI][2];
#pragma unroll
            for (int mi = 0; mi < MI; mi++) {
                int r = wr + mi * 16 + g;
                a[mi][0] = f2tf(Ab[r * AS_STRIDE + kb + t]);
                a[mi][1] = f2tf(Ab[(r + 8) * AS_STRIDE + kb + t]);
                a[mi][2] = f2tf(Ab[r * AS_STRIDE + kb + t + 4]);
                a[mi][3] = f2tf(Ab[(r + 8) * AS_STRIDE + kb + t + 4]);
            }
#pragma unroll
            for (int ni = 0; ni < NI; ni++) {
                int cn = wc + ni * 8 + g;
                b[ni][0] = f2tf(Bb[(kb + t) * BS_STRIDE + cn]);
                b[ni][1] = f2tf(Bb[(kb + t + 4) * BS_STRIDE + cn]);
            }
#pragma unroll
            for (int mi = 0; mi < MI; mi++)
#pragma unroll
                for (int ni = 0; ni < NI; ni++) {
                    asm volatile(
                        "mma.sync.aligned.m16n8k8.row.col.f32.tf32.tf32.f32 "
                        "{%0,%1,%2,%3}, {%4,%5,%6,%7}, {%8,%9}, {%0,%1,%2,%3};"
                        : "+f"(acc[mi][ni][0]), "+f"(acc[mi][ni][1]),
                          "+f"(acc[mi][ni][2]), "+f"(acc[mi][ni][3])
                        : "r"(a[mi][0]), "r"(a[mi][1]), "r"(a[mi][2]), "r"(a[mi][3]),
                          "r"(b[ni][0]), "r"(b[ni][1]));
                }
        }
        __syncthreads();   // all warps done reading buf before it is overwritten
    }

#pragma unroll
    for (int mi = 0; mi < MI; mi++) {
        int r0 = rowBase + wr + mi * 16 + g;
#pragma unroll
        for (int half = 0; half < 2; half++) {
            int r = r0 + half * 8;
            if (r >= M) continue;
#pragma unroll
            for (int ni = 0; ni < NI; ni++) {
                int col = colBase + wc + ni * 8 + 2 * t;
                float v0 = acc[mi][ni][half * 2 + 0] + bias[col];
                float v1 = acc[mi][ni][half * 2 + 1] + bias[col + 1];
                if (relu) {
                    v0 = fmaxf(v0, 0.f);
                    v1 = fmaxf(v1, 0.f);
                }
                *(float2*)(C + (size_t)r * N + col) = make_float2(v0, v1);
            }
        }
    }
}

#define GEMM_SMEM_128 ((2 * 128 * AS_STRIDE + 2 * 32 * (128 + 8)) * 4)
#define GEMM_SMEM_64  ((2 * 64 * AS_STRIDE + 2 * 32 * (64 + 8)) * 4)

// ---------------- global max pool (batch is sorted) ----------------
__global__ void k_gstart(const int* __restrict__ batch, int* __restrict__ gstart) {
    int i = blockIdx.x * blockDim.x + threadIdx.x;
    if (i >= NN) return;
    if (i == 0) {
        gstart[0] = 0;
        gstart[NG] = NN;
    } else if (batch[i] != batch[i - 1]) {
        gstart[batch[i]] = i;
    }
}

__global__ void k_pool_max(const float* __restrict__ h, const int* __restrict__ gstart,
                           float* __restrict__ g) {
    int gr = blockIdx.x;
    int f = threadIdx.x;
    int s = gstart[gr], e = gstart[gr + 1];
    float m = -3.4e38f;
    for (int i = s; i < e; i++) m = fmaxf(m, h[(size_t)i * 512 + f]);
    g[gr * 512 + f] = m;
}

// ---------------- launch ----------------
extern "C" void kernel_launch(void* const* d_in, const int* in_sizes, int n_in,
                              void* d_out, int out_size) {
    const float* x   = (const float*)d_in[0];
    const float* ew  = (const float*)d_in[1];
    const float* W1  = (const float*)d_in[2];
    const float* b1  = (const float*)d_in[3];
    const float* W2  = (const float*)d_in[4];
    const float* b2  = (const float*)d_in[5];
    const float* W3  = (const float*)d_in[6];
    const float* b3  = (const float*)d_in[7];
    const float* Wf1 = (const float*)d_in[8];
    const float* bf1 = (const float*)d_in[9];
    const float* Wf2 = (const float*)d_in[10];
    const float* bf2 = (const float*)d_in[11];
    const int* ei    = (const int*)d_in[12];    // int32 (JAX x64 disabled)
    const int* batch = (const int*)d_in[13];    // int32
    float* out = (float*)d_out;

    void *p;
    cudaGetSymbolAddress(&p, g_deg);    float* deg   = (float*)p;
    cudaGetSymbolAddress(&p, g_dinv);   float* dinv  = (float*)p;
    cudaGetSymbolAddress(&p, g_cnt);    int*   cnt   = (int*)p;
    cudaGetSymbolAddress(&p, g_rowptr); int*   rowp  = (int*)p;
    cudaGetSymbolAddress(&p, g_part);   int*   part  = (int*)p;
    cudaGetSymbolAddress(&p, g_esrc);   int*   esrc  = (int*)p;
    cudaGetSymbolAddress(&p, g_ecoef);  float* ecoef = (float*)p;
    cudaGetSymbolAddress(&p, g_agg);    float* agg   = (float*)p;
    cudaGetSymbolAddress(&p, g_h1);     float* h1    = (float*)p;
    cudaGetSymbolAddress(&p, g_h2);     float* h2    = (float*)p;
    cudaGetSymbolAddress(&p, g_h3);     float* h3    = (float*)p;
    cudaGetSymbolAddress(&p, g_pool);   float* pool  = (float*)p;
    cudaGetSymbolAddress(&p, g_fc1);    float* fc1   = (float*)p;
    cudaGetSymbolAddress(&p, g_gstart); int*   gst   = (int*)p;

    static bool attrSet = false;
    if (!attrSet) {
        cudaFuncSetAttribute(k_gemm_tf32<128, 128>,
                             cudaFuncAttributeMaxDynamicSharedMemorySize, GEMM_SMEM_128);
        cudaFuncSetAttribute(k_gemm_tf32<64, 64>,
                             cudaFuncAttributeMaxDynamicSharedMemorySize, GEMM_SMEM_64);
        attrSet = true;
    }

    const int T = 256;
    // ---- normalization prep + CSR build ----
    k_deg_init<<<(NN + T - 1) / T, T>>>(deg, cnt);
    k_deg_edges<<<(NE + T - 1) / T, T>>>(ei, ew, deg, cnt);
    k_scan_part<<<SCAN_B, 256>>>(cnt, part);
    k_scan_top<<<1, SCAN_B>>>(part, rowp);
    k_scan_fin<<<SCAN_B, 256>>>(cnt, part, rowp, deg, dinv);
    k_edge_scatter<<<(NE + T - 1) / T, T>>>(ei, ew, dinv, rowp, cnt, esrc, ecoef);

    const int MB = (NN + 127) / 128;       // 391 row tiles
    const int GW = (NN * 32 + T - 1) / T;  // gather: warp per node

    // ---- layer 1 ----
    k_gather<128><<<GW, T>>>(rowp, esrc, ecoef, dinv, x, agg);
    k_gemm_tf32<128, 128><<<dim3(1, MB), 128, GEMM_SMEM_128>>>(agg, W1, b1, h1, NN, 128, 128, 1);

    // ---- layer 2 ----
    k_gather<128><<<GW, T>>>(rowp, esrc, ecoef, dinv, h1, agg);
    k_gemm_tf32<128, 128><<<dim3(2, MB), 128, GEMM_SMEM_128>>>(agg, W2, b2, h2, NN, 256, 128, 1);

    // ---- layer 3 ----
    k_gather<256><<<GW, T>>>(rowp, esrc, ecoef, dinv, h2, agg);
    k_gemm_tf32<128, 128><<<dim3(4, MB), 128, GEMM_SMEM_128>>>(agg, W3, b3, h3, NN, 512, 256, 1);

    // ---- global max pool ----
    k_gstart<<<(NN + T - 1) / T, T>>>(batch, gst);
    k_pool_max<<<NG, 512>>>(h3, gst, pool);

    // ---- FC head ----
    k_gemm_tf32<64, 64><<<dim3(1024 / 64, NG / 64), 128, GEMM_SMEM_64>>>(pool, Wf1, bf1, fc1, NG, 1024, 512, 1);
    k_gemm_tf32<64, 64><<<dim3(128 / 64, NG / 64), 128, GEMM_SMEM_64>>>(fc1, Wf2, bf2, out, NG, 128, 1024, 0);
}